// round 2
// baseline (speedup 1.0000x reference)
#include <cuda_runtime.h>
#include <cuda_bf16.h>
#include <cstdint>

// ---------------- problem constants ----------------
#define B_   256
#define K_   32
#define M_   64
#define MN_  256
#define E_   128
#define H_   128
#define Q_   128

// ---------------- scratch (device globals: zero-initialized at load) --------
__device__ float g_init  [B_ * H_];        // lrelu(hidden(ent[start]))
__device__ float g_pnode [B_ * H_];        // pass_W[:, :H] @ init   (no bias)
__device__ float g_relsum[B_ * K_ * E_];   // (sum rel_emb over kept m) / denom
__device__ float g_c0d   [B_ * K_];        // cnt0 / denom
__device__ float g_cd    [B_ * K_];        // cnt  / denom
__device__ float g_upd   [B_ * K_ * H_];   // updated node embeddings (rows 1..K)
__device__ float g_state [B_ * H_];        // next_hop state
__device__ float g_zero  [H_];             // stays zero -> "node index > K" rows

__device__ __forceinline__ float lrelu(float x) { return x >= 0.f ? x : 0.01f * x; }

// ============================================================================
// Kernel 1: init[b] = lrelu(hidden_W @ ent[start[b]] + hidden_b)
//           pnode[b] = pass_W[:, :H] @ init[b]
// ============================================================================
__global__ void k1_init(const int* __restrict__ start,
                        const float* __restrict__ ent,
                        const float* __restrict__ hW,
                        const float* __restrict__ hb,
                        const float* __restrict__ pW)
{
    int b = blockIdx.x, t = threadIdx.x;
    __shared__ float xs[E_];
    __shared__ float iv[H_];
    xs[t] = ent[(long)start[b] * E_ + t];
    __syncthreads();

    float acc = 0.f;
    const float* wr = hW + t * E_;
    #pragma unroll 8
    for (int e = 0; e < E_; e++) acc += wr[e] * xs[e];
    float v = lrelu(acc + hb[t]);
    iv[t] = v;
    g_init[b * H_ + t] = v;
    __syncthreads();

    float p = 0.f;
    const float* pr = pW + t * (H_ + E_);   // first H columns of pass_W row t
    #pragma unroll 8
    for (int e = 0; e < H_; e++) p += pr[e] * iv[e];
    g_pnode[b * H_ + t] = p;
}

// ============================================================================
// Kernel 2: per (b,k): relsum/denom, cnt0/denom, cnt/denom
// ============================================================================
__global__ void k2_relsum(const int* __restrict__ nb_nodes,
                          const int* __restrict__ nb_rels,
                          const int* __restrict__ nb_num,
                          const float* __restrict__ rel_emb)
{
    int r = blockIdx.x, t = threadIdx.x;
    __shared__ int s_rel[M_];
    __shared__ int s_c0;
    if (t == 0) s_c0 = 0;
    int cnt = nb_num[r];
    if (cnt < 0)  cnt = 0;
    if (cnt > M_) cnt = M_;
    if (t < M_) s_rel[t] = nb_rels[r * M_ + t];
    __syncthreads();
    if (t < cnt && nb_nodes[r * M_ + t] == 0) atomicAdd(&s_c0, 1);

    float acc = 0.f;
    for (int m = 0; m < cnt; m++)
        acc += rel_emb[s_rel[m] * E_ + t];
    __syncthreads();

    float denom = (cnt == 0) ? 1.f : (float)cnt;
    g_relsum[r * E_ + t] = acc / denom;
    if (t == 0) {
        g_c0d[r] = (float)s_c0 / denom;
        g_cd[r]  = (float)cnt  / denom;
    }
}

// ============================================================================
// GEMM tiling: BM=128 rows, BN=128 cols, BK=32, 256 threads, 8x8 reg tile
// thread (ty,tx): rows ty*8+i, cols tx+16*j  (conflict-free smem reads)
// smem pad 33: store bank = (row + kk) mod 32 -> conflict-free f4 scatter
// ============================================================================
#define BM 128
#define BN 128
#define BK 32

// ============================================================================
// Kernel 3: upd[r] = lrelu( [hidden_W | pass_W[:,H:]] @ [aim_e ; relsum/denom]
//                           + hidden_b + c0d*pnode[b] + cd*pass_b )
// rows R = B*K = 8192, K = 256, N = 128.  grid(64), block(256)
// ============================================================================
__global__ __launch_bounds__(256)
void k3_upd(const int* __restrict__ aims,
            const float* __restrict__ ent,
            const float* __restrict__ hW,
            const float* __restrict__ pW,
            const float* __restrict__ hb,
            const float* __restrict__ pb)
{
    __shared__ float Xs[BM][BK + 1];
    __shared__ float Ws[BN][BK + 1];
    __shared__ const float* rowp[BM];
    __shared__ float s_c0d[BM], s_cd[BM];

    int t = threadIdx.x;
    int rr0 = blockIdx.x * BM;
    if (t < BM) {
        int rr = rr0 + t;
        rowp[t]  = ent + (long)aims[rr] * E_;
        s_c0d[t] = g_c0d[rr];
        s_cd[t]  = g_cd[rr];
    }
    __syncthreads();

    int ty = t >> 4, tx = t & 15;
    float acc[8][8];
    #pragma unroll
    for (int i = 0; i < 8; i++)
        #pragma unroll
        for (int j = 0; j < 8; j++) acc[i][j] = 0.f;

    for (int k0 = 0; k0 < H_ + E_; k0 += BK) {
        #pragma unroll
        for (int i = 0; i < 4; i++) {              // 128x32 X tile (1024 f4)
            int idx = t + i * 256;
            int row = idx >> 3, c4 = idx & 7;
            const float* src = (k0 < 128) ? (rowp[row] + k0)
                                          : (g_relsum + (rr0 + row) * E_ + (k0 - 128));
            float4 v = *(const float4*)(src + c4 * 4);
            int kk = c4 * 4;
            Xs[row][kk] = v.x; Xs[row][kk+1] = v.y; Xs[row][kk+2] = v.z; Xs[row][kk+3] = v.w;
        }
        #pragma unroll
        for (int i = 0; i < 4; i++) {              // 128x32 W tile (1024 f4)
            int idx = t + i * 256;
            int n = idx >> 3, c4 = idx & 7;
            const float* src = (k0 < 128) ? (hW + n * 128 + k0)
                                          : (pW + n * 256 + k0);   // pass_W cols 128..255
            float4 v = *(const float4*)(src + c4 * 4);
            int kk = c4 * 4;
            Ws[n][kk] = v.x; Ws[n][kk+1] = v.y; Ws[n][kk+2] = v.z; Ws[n][kk+3] = v.w;
        }
        __syncthreads();
        #pragma unroll
        for (int kk = 0; kk < BK; kk++) {
            float xr[8], wr[8];
            #pragma unroll
            for (int i = 0; i < 8; i++) xr[i] = Xs[ty * 8 + i][kk];
            #pragma unroll
            for (int j = 0; j < 8; j++) wr[j] = Ws[tx + 16 * j][kk];
            #pragma unroll
            for (int i = 0; i < 8; i++)
                #pragma unroll
                for (int j = 0; j < 8; j++) acc[i][j] += xr[i] * wr[j];
        }
        __syncthreads();
    }

    #pragma unroll
    for (int i = 0; i < 8; i++) {
        int row = ty * 8 + i;
        int rr  = rr0 + row;
        int b   = rr >> 5;                // rr / K_
        #pragma unroll
        for (int j = 0; j < 8; j++) {
            int n = tx + 16 * j;
            float v = acc[i][j] + hb[n]
                    + s_c0d[row] * g_pnode[b * H_ + n]
                    + s_cd[row]  * pb[n];
            g_upd[rr * H_ + n] = lrelu(v);
        }
    }
}

// ============================================================================
// Kernel 4: cur lookup, state = lrelu(nexthop([cur;query])), thresh -> out[:,MN]
// ============================================================================
__global__ void k4_state(const int* __restrict__ currents,
                         const float* __restrict__ query,
                         const float* __restrict__ nW,
                         const float* __restrict__ nb,
                         const float* __restrict__ gW,
                         const float* __restrict__ gb,
                         float* __restrict__ out)
{
    int b = blockIdx.x, t = threadIdx.x;
    __shared__ float cc[H_ + Q_];
    __shared__ float red[128];

    int c = currents[b];
    float cur;
    if (c == 0)                 cur = g_init[b * H_ + t];
    else if (c >= 1 && c <= K_) cur = g_upd[(b * K_ + (c - 1)) * H_ + t];
    else                        cur = 0.f;
    cc[t]      = cur;
    cc[H_ + t] = query[b * Q_ + t];
    __syncthreads();

    float acc = 0.f;
    const float* wr = nW + t * (H_ + Q_);
    #pragma unroll 8
    for (int e = 0; e < H_ + Q_; e++) acc += wr[e] * cc[e];
    g_state[b * H_ + t] = lrelu(acc + nb[t]);

    red[t] = gW[t] * cc[t] + gW[H_ + t] * cc[H_ + t];
    __syncthreads();
    for (int s = 64; s > 0; s >>= 1) {
        if (t < s) red[t] += red[t + s];
        __syncthreads();
    }
    if (t == 0) out[b * (MN_ + 1) + MN_] = red[0] + gb[0];
}

// ============================================================================
// Kernel 5: fused candidate GEMM + lrelu + dot(state) + mask + scale
// rows R = B*MN = 65536, K = 384, N = 128.  grid(512), block(256)
// NOTE: candidate_masks arrives as int32 (bool upcast by harness).
// ============================================================================
__global__ __launch_bounds__(256)
void k5_cand(const int* __restrict__ cnodes,
             const int* __restrict__ cents,
             const int* __restrict__ crels,
             const int* __restrict__ cmask,
             const float* __restrict__ ent,
             const float* __restrict__ rel,
             const float* __restrict__ cW,
             const float* __restrict__ cb,
             float* __restrict__ out)
{
    __shared__ float Xs[BM][BK + 1];
    __shared__ float Ws[BN][BK + 1];
    __shared__ const float* pN[BM];
    __shared__ const float* pE[BM];
    __shared__ const float* pR[BM];
    __shared__ float s_state[H_];

    int t = threadIdx.x;
    int rr0 = blockIdx.x * BM;
    int b = rr0 >> 8;                      // 128 | 256 -> single b per block

    if (t < BM) {
        int rr = rr0 + t;
        int node = cnodes[rr];
        const float* p;
        if (node == 0)                    p = g_init + b * H_;
        else if (node >= 1 && node <= K_) p = g_upd + (b * K_ + (node - 1)) * H_;
        else                              p = g_zero;
        pN[t] = p;
        pE[t] = ent + (long)cents[rr] * E_;
        pR[t] = rel + (long)crels[rr] * E_;
    }
    if (t < H_) s_state[t] = g_state[b * H_ + t];
    __syncthreads();

    int ty = t >> 4, tx = t & 15;
    float acc[8][8];
    #pragma unroll
    for (int i = 0; i < 8; i++)
        #pragma unroll
        for (int j = 0; j < 8; j++) acc[i][j] = 0.f;

    for (int k0 = 0; k0 < H_ + 2 * E_; k0 += BK) {
        const float* const* ptab;
        int kof;
        if (k0 < 128)      { ptab = pN; kof = k0; }
        else if (k0 < 256) { ptab = pE; kof = k0 - 128; }
        else               { ptab = pR; kof = k0 - 256; }
        #pragma unroll
        for (int i = 0; i < 4; i++) {              // X tile
            int idx = t + i * 256;
            int row = idx >> 3, c4 = idx & 7;
            float4 v = *(const float4*)(ptab[row] + kof + c4 * 4);
            int kk = c4 * 4;
            Xs[row][kk] = v.x; Xs[row][kk+1] = v.y; Xs[row][kk+2] = v.z; Xs[row][kk+3] = v.w;
        }
        #pragma unroll
        for (int i = 0; i < 4; i++) {              // W tile
            int idx = t + i * 256;
            int n = idx >> 3, c4 = idx & 7;
            float4 v = *(const float4*)(cW + n * 384 + k0 + c4 * 4);
            int kk = c4 * 4;
            Ws[n][kk] = v.x; Ws[n][kk+1] = v.y; Ws[n][kk+2] = v.z; Ws[n][kk+3] = v.w;
        }
        __syncthreads();
        #pragma unroll
        for (int kk = 0; kk < BK; kk++) {
            float xr[8], wr[8];
            #pragma unroll
            for (int i = 0; i < 8; i++) xr[i] = Xs[ty * 8 + i][kk];
            #pragma unroll
            for (int j = 0; j < 8; j++) wr[j] = Ws[tx + 16 * j][kk];
            #pragma unroll
            for (int i = 0; i < 8; i++)
                #pragma unroll
                for (int j = 0; j < 8; j++) acc[i][j] += xr[i] * wr[j];
        }
        __syncthreads();
    }

    // epilogue: lrelu + bias, weight by state, reduce across tx (16 lanes)
    #pragma unroll
    for (int i = 0; i < 8; i++) {
        float rsum = 0.f;
        #pragma unroll
        for (int j = 0; j < 8; j++) {
            int n = tx + 16 * j;
            float v = lrelu(acc[i][j] + cb[n]);
            rsum += v * s_state[n];
        }
        // reduce over the 16 tx lanes (lanes [0..15] or [16..31] of the warp)
        #pragma unroll
        for (int m = 8; m > 0; m >>= 1)
            rsum += __shfl_xor_sync(0xFFFFFFFFu, rsum, m, 32);
        if (tx == 0) {
            int rr = rr0 + ty * 8 + i;
            float s = rsum * 0.08838834764831845f;          // 1/sqrt(128)
            float o = cmask[rr] ? s : -100000.f;
            out[b * (MN_ + 1) + (rr & 255)] = o;
        }
    }
}

// ============================================================================
// launch
// ============================================================================
extern "C" void kernel_launch(void* const* d_in, const int* in_sizes, int n_in,
                              void* d_out, int out_size)
{
    const int*   start_entities      = (const int*)  d_in[0];
    const int*   aims                = (const int*)  d_in[1];
    /* node_pos = d_in[2]: always arange(1..K), folded into indexing */
    const int*   neighbor_nodes      = (const int*)  d_in[3];
    const int*   neighbor_relations  = (const int*)  d_in[4];
    const int*   neighbors_num       = (const int*)  d_in[5];
    const int*   currents            = (const int*)  d_in[6];
    const int*   candidate_nodes     = (const int*)  d_in[7];
    const int*   candidate_entities  = (const int*)  d_in[8];
    const int*   candidate_relations = (const int*)  d_in[9];
    const int*   candidate_masks     = (const int*)  d_in[10];   // bool -> int32
    const float* entity_emb          = (const float*)d_in[11];
    const float* relation_emb        = (const float*)d_in[12];
    const float* hidden_W            = (const float*)d_in[13];
    const float* hidden_b            = (const float*)d_in[14];
    const float* pass_W              = (const float*)d_in[15];
    const float* pass_b              = (const float*)d_in[16];
    const float* nexthop_W           = (const float*)d_in[17];
    const float* nexthop_b           = (const float*)d_in[18];
    const float* candidate_W         = (const float*)d_in[19];
    const float* candidate_b         = (const float*)d_in[20];
    const float* gate_W              = (const float*)d_in[21];
    const float* gate_b              = (const float*)d_in[22];
    const float* query               = (const float*)d_in[23];
    float* out = (float*)d_out;

    k1_init  <<<B_,       128>>>(start_entities, entity_emb, hidden_W, hidden_b, pass_W);
    k2_relsum<<<B_ * K_,  128>>>(neighbor_nodes, neighbor_relations, neighbors_num, relation_emb);
    k3_upd   <<<(B_ * K_) / BM, 256>>>(aims, entity_emb, hidden_W, pass_W, hidden_b, pass_b);
    k4_state <<<B_,       128>>>(currents, query, nexthop_W, nexthop_b, gate_W, gate_b, out);
    k5_cand  <<<(B_ * MN_) / BM, 256>>>(candidate_nodes, candidate_entities, candidate_relations,
                                        candidate_masks, entity_emb, relation_emb,
                                        candidate_W, candidate_b, out);
}

// round 4
// speedup vs baseline: 2.0385x; 2.0385x over previous
#include <cuda_runtime.h>
#include <cuda_bf16.h>
#include <cstdint>

// ---------------- problem constants ----------------
#define B_   256
#define K_   32
#define M_   64
#define MN_  256
#define E_   128
#define H_   128
#define Q_   128

// ---------------- scratch (device globals) ----------------
__device__ float g_init  [B_ * H_];
__device__ float g_pnode [B_ * H_];
__device__ float g_relsum[B_ * K_ * E_];
__device__ float g_c0d   [B_ * K_];
__device__ float g_cd    [B_ * K_];
__device__ float g_upd   [B_ * K_ * H_];
__device__ float g_state [B_ * H_];
__device__ float g_cc    [B_ * (H_ + Q_)];
__device__ float g_nWT   [(H_ + Q_) * H_];      // nexthop_W transposed
__device__ float g_zero  [H_];                  // stays zero
__device__ __nv_bfloat16 g_cWb[H_ * 384];       // candidate_W in bf16

__device__ __forceinline__ float lrelu(float x) { return x >= 0.f ? x : 0.01f * x; }

// warp-level bf16 tensor-core mma (sm_80+ baseline PTX -> HMMA on Blackwell)
__device__ __forceinline__ void mma16816(float* c, const uint32_t* a, const uint32_t* b) {
    asm volatile(
        "mma.sync.aligned.m16n8k16.row.col.f32.bf16.bf16.f32 "
        "{%0,%1,%2,%3}, {%4,%5,%6,%7}, {%8,%9}, {%0,%1,%2,%3};"
        : "+f"(c[0]), "+f"(c[1]), "+f"(c[2]), "+f"(c[3])
        : "r"(a[0]), "r"(a[1]), "r"(a[2]), "r"(a[3]), "r"(b[0]), "r"(b[1]));
}

// ============================================================================
// Kernel P: convert candidate_W (128x384 fp32) -> bf16
// ============================================================================
__global__ void kprep_cw(const float* __restrict__ cW) {
    int i = blockIdx.x * 256 + threadIdx.x;
    if (i < H_ * 384) g_cWb[i] = __float2bfloat16(cW[i]);
}

// ============================================================================
// Kernel 1: init + pnode
// ============================================================================
__global__ void k1_init(const int* __restrict__ start, const float* __restrict__ ent,
                        const float* __restrict__ hW, const float* __restrict__ hb,
                        const float* __restrict__ pW)
{
    int b = blockIdx.x, t = threadIdx.x;
    __shared__ float xs[E_], iv[H_];
    xs[t] = ent[(long)start[b] * E_ + t];
    __syncthreads();
    float acc = 0.f;
    const float* wr = hW + t * E_;
    #pragma unroll 8
    for (int e = 0; e < E_; e++) acc += wr[e] * xs[e];
    float v = lrelu(acc + hb[t]);
    iv[t] = v;
    g_init[b * H_ + t] = v;
    __syncthreads();
    float p = 0.f;
    const float* pr = pW + t * (H_ + E_);
    #pragma unroll 8
    for (int e = 0; e < H_; e++) p += pr[e] * iv[e];
    g_pnode[b * H_ + t] = p;
}

// ============================================================================
// Kernel 2: relsum / counts
// ============================================================================
__global__ void k2_relsum(const int* __restrict__ nb_nodes, const int* __restrict__ nb_rels,
                          const int* __restrict__ nb_num, const float* __restrict__ rel_emb)
{
    int r = blockIdx.x, t = threadIdx.x;
    __shared__ int s_rel[M_];
    __shared__ int s_c0;
    if (t == 0) s_c0 = 0;
    int cnt = nb_num[r];
    if (cnt < 0)  cnt = 0;
    if (cnt > M_) cnt = M_;
    if (t < M_) s_rel[t] = nb_rels[r * M_ + t];
    __syncthreads();
    if (t < cnt && nb_nodes[r * M_ + t] == 0) atomicAdd(&s_c0, 1);
    float acc = 0.f;
    for (int m = 0; m < cnt; m++) acc += rel_emb[s_rel[m] * E_ + t];
    __syncthreads();
    float denom = (cnt == 0) ? 1.f : (float)cnt;
    g_relsum[r * E_ + t] = acc / denom;
    if (t == 0) { g_c0d[r] = (float)s_c0 / denom; g_cd[r] = (float)cnt / denom; }
}

// ============================================================================
// Kernel 3 (SIMT fp32): upd GEMM  R=8192, K=256, N=128
// ============================================================================
#define BM3 128
#define BK3 32
__global__ __launch_bounds__(256)
void k3_upd(const int* __restrict__ aims, const float* __restrict__ ent,
            const float* __restrict__ hW, const float* __restrict__ pW,
            const float* __restrict__ hb, const float* __restrict__ pb)
{
    __shared__ float Xs[BM3][BK3 + 1];
    __shared__ float Ws[128][BK3 + 1];
    __shared__ const float* rowp[BM3];
    __shared__ float s_c0d[BM3], s_cd[BM3];

    int t = threadIdx.x;
    int rr0 = blockIdx.x * BM3;
    if (t < BM3) {
        int rr = rr0 + t;
        rowp[t] = ent + (long)aims[rr] * E_;
        s_c0d[t] = g_c0d[rr];
        s_cd[t]  = g_cd[rr];
    }
    __syncthreads();

    int ty = t >> 4, tx = t & 15;
    float acc[8][8];
    #pragma unroll
    for (int i = 0; i < 8; i++)
        #pragma unroll
        for (int j = 0; j < 8; j++) acc[i][j] = 0.f;

    for (int k0 = 0; k0 < H_ + E_; k0 += BK3) {
        #pragma unroll
        for (int i = 0; i < 4; i++) {
            int idx = t + i * 256;
            int row = idx >> 3, c4 = idx & 7;
            const float* src = (k0 < 128) ? (rowp[row] + k0)
                                          : (g_relsum + (rr0 + row) * E_ + (k0 - 128));
            float4 v = *(const float4*)(src + c4 * 4);
            int kk = c4 * 4;
            Xs[row][kk] = v.x; Xs[row][kk+1] = v.y; Xs[row][kk+2] = v.z; Xs[row][kk+3] = v.w;
        }
        #pragma unroll
        for (int i = 0; i < 4; i++) {
            int idx = t + i * 256;
            int n = idx >> 3, c4 = idx & 7;
            const float* src = (k0 < 128) ? (hW + n * 128 + k0) : (pW + n * 256 + k0);
            float4 v = *(const float4*)(src + c4 * 4);
            int kk = c4 * 4;
            Ws[n][kk] = v.x; Ws[n][kk+1] = v.y; Ws[n][kk+2] = v.z; Ws[n][kk+3] = v.w;
        }
        __syncthreads();
        #pragma unroll
        for (int kk = 0; kk < BK3; kk++) {
            float xr[8], wr[8];
            #pragma unroll
            for (int i = 0; i < 8; i++) xr[i] = Xs[ty * 8 + i][kk];
            #pragma unroll
            for (int j = 0; j < 8; j++) wr[j] = Ws[tx + 16 * j][kk];
            #pragma unroll
            for (int i = 0; i < 8; i++)
                #pragma unroll
                for (int j = 0; j < 8; j++) acc[i][j] += xr[i] * wr[j];
        }
        __syncthreads();
    }
    #pragma unroll
    for (int i = 0; i < 8; i++) {
        int row = ty * 8 + i;
        int rr = rr0 + row, b = rr >> 5;
        #pragma unroll
        for (int j = 0; j < 8; j++) {
            int n = tx + 16 * j;
            float v = acc[i][j] + hb[n] + s_c0d[row] * g_pnode[b * H_ + n] + s_cd[row] * pb[n];
            g_upd[rr * H_ + n] = lrelu(v);
        }
    }
}

// ============================================================================
// Kernel 4a: build cc[b] = [cur ; query], gate -> out[:, MN]
// ============================================================================
__global__ void k4a_cc(const int* __restrict__ currents, const float* __restrict__ query,
                       const float* __restrict__ gW, const float* __restrict__ gb,
                       float* __restrict__ out)
{
    int b = blockIdx.x, t = threadIdx.x;
    __shared__ float red[128];
    int c = currents[b];
    float cur;
    if (c == 0)                 cur = g_init[b * H_ + t];
    else if (c >= 1 && c <= K_) cur = g_upd[(b * K_ + (c - 1)) * H_ + t];
    else                        cur = 0.f;
    float q = query[b * Q_ + t];
    g_cc[b * 256 + t]       = cur;
    g_cc[b * 256 + 128 + t] = q;
    red[t] = gW[t] * cur + gW[128 + t] * q;
    __syncthreads();
    for (int s = 64; s > 0; s >>= 1) {
        if (t < s) red[t] += red[t + s];
        __syncthreads();
    }
    if (t == 0) out[b * (MN_ + 1) + MN_] = red[0] + gb[0];
}

// ============================================================================
// Kernel 4t: transpose nexthop_W (128x256) -> g_nWT (256x128)
// ============================================================================
__global__ void k4t_trans(const float* __restrict__ nW) {
    int i = blockIdx.x * 256 + threadIdx.x;
    if (i < 256 * 128) {
        int e = i >> 7, n = i & 127;
        g_nWT[i] = nW[n * 256 + e];
    }
}

// ============================================================================
// Kernel 4c: state[b][n] = lrelu( sum_e cc[b][e] * nWT[e][n] + nbias[n] )
// ============================================================================
__global__ void k4c_state(const float* __restrict__ nbias)
{
    int b = blockIdx.x, n = threadIdx.x;
    __shared__ float s_cc[256];
    s_cc[n] = g_cc[b * 256 + n];
    s_cc[128 + n] = g_cc[b * 256 + 128 + n];
    __syncthreads();
    float acc = 0.f;
    #pragma unroll 8
    for (int e = 0; e < 256; e++) acc += s_cc[e] * g_nWT[e * 128 + n];
    g_state[b * H_ + n] = lrelu(acc + nbias[n]);
}

// ============================================================================
// Kernel 5: warp-mma bf16 candidate GEMM + fused epilogue
//   per CTA: M=128 gathered rows, N=128, K=384 in 6 tiles of BK=64
//   8 warps: warp w -> rows [w*16, w*16+16), all 128 cols
//   grid(512), block(256)
// ============================================================================
#define PITCH5 72   // 64 bf16 + 8 pad -> 144B rows, +4 banks/row, conflict-free
__global__ __launch_bounds__(256)
void k5_cand(const int* __restrict__ cnodes, const int* __restrict__ cents,
             const int* __restrict__ crels, const int* __restrict__ cmask,
             const float* __restrict__ ent, const float* __restrict__ rel,
             const float* __restrict__ cb, float* __restrict__ out)
{
    __shared__ __nv_bfloat16 As[128 * PITCH5];   // 18432 B
    __shared__ __nv_bfloat16 Bs[128 * PITCH5];   // 18432 B
    __shared__ const float* pN[128];
    __shared__ const float* pE[128];
    __shared__ const float* pR[128];
    __shared__ float s_state[H_], s_cb[H_];

    int t    = threadIdx.x;
    int wid  = t >> 5, lane = t & 31;
    int l4   = lane >> 2, lp2 = (lane & 3) * 2;
    int wrow = wid * 16;
    int rr0  = blockIdx.x * 128;
    int b    = rr0 >> 8;

    if (t < 128) {
        int rr = rr0 + t;
        int node = cnodes[rr];
        const float* p;
        if (node == 0)                    p = g_init + b * H_;
        else if (node >= 1 && node <= K_) p = g_upd + (b * K_ + (node - 1)) * H_;
        else                              p = g_zero;
        pN[t] = p;
        pE[t] = ent + (long)cents[rr] * E_;
        pR[t] = rel + (long)crels[rr] * E_;
        s_state[t] = g_state[b * H_ + t];
        s_cb[t]    = cb[t];
    }
    __syncthreads();

    float acc[64];
    #pragma unroll
    for (int i = 0; i < 64; i++) acc[i] = 0.f;

    #pragma unroll
    for (int j = 0; j < 6; j++) {
        int seg = j >> 1;
        int kof = (j & 1) * 64;
        const float* const* ptab = (seg == 0) ? pN : (seg == 1) ? pE : pR;

        // ---- A tile: 128 rows x 64 cols fp32 -> bf16 (4 chunks of 8/thread) ----
        #pragma unroll
        for (int i = 0; i < 4; i++) {
            int id  = t + i * 256;
            int row = id >> 3, c0 = (id & 7) * 8;
            const float* src = ptab[row] + kof + c0;
            float4 va = *(const float4*)(src);
            float4 vb = *(const float4*)(src + 4);
            __nv_bfloat162 p0 = __floats2bfloat162_rn(va.x, va.y);
            __nv_bfloat162 p1 = __floats2bfloat162_rn(va.z, va.w);
            __nv_bfloat162 p2 = __floats2bfloat162_rn(vb.x, vb.y);
            __nv_bfloat162 p3 = __floats2bfloat162_rn(vb.z, vb.w);
            uint4 u;
            u.x = *(uint32_t*)&p0; u.y = *(uint32_t*)&p1;
            u.z = *(uint32_t*)&p2; u.w = *(uint32_t*)&p3;
            *(uint4*)(As + row * PITCH5 + c0) = u;
        }
        // ---- B tile: 128 rows (n) x 64 cols (k) bf16 ----
        #pragma unroll
        for (int i = 0; i < 4; i++) {
            int id  = t + i * 256;
            int n = id >> 3, c0 = (id & 7) * 8;
            uint4 u = *(const uint4*)(g_cWb + n * 384 + j * 64 + c0);
            *(uint4*)(Bs + n * PITCH5 + c0) = u;
        }
        __syncthreads();

        // ---- 4 k16-steps of mma ----
        #pragma unroll
        for (int ks = 0; ks < 4; ks++) {
            int k0 = ks * 16;
            uint32_t a[4];
            a[0] = *(const uint32_t*)(As + (wrow + l4)     * PITCH5 + k0 + lp2);
            a[1] = *(const uint32_t*)(As + (wrow + l4 + 8) * PITCH5 + k0 + lp2);
            a[2] = *(const uint32_t*)(As + (wrow + l4)     * PITCH5 + k0 + lp2 + 8);
            a[3] = *(const uint32_t*)(As + (wrow + l4 + 8) * PITCH5 + k0 + lp2 + 8);
            #pragma unroll
            for (int nt = 0; nt < 16; nt++) {
                uint32_t bb[2];
                bb[0] = *(const uint32_t*)(Bs + (nt * 8 + l4) * PITCH5 + k0 + lp2);
                bb[1] = *(const uint32_t*)(Bs + (nt * 8 + l4) * PITCH5 + k0 + lp2 + 8);
                mma16816(acc + nt * 4, a, bb);
            }
        }
        __syncthreads();
    }

    // ---- epilogue: lrelu+bias, dot(state); c-frag rows = wrow+l4, wrow+l4+8 ----
    float rlo = 0.f, rhi = 0.f;
    #pragma unroll
    for (int nt = 0; nt < 16; nt++) {
        int c0 = nt * 8 + lp2, c1 = c0 + 1;
        rlo += lrelu(acc[nt * 4 + 0] + s_cb[c0]) * s_state[c0]
             + lrelu(acc[nt * 4 + 1] + s_cb[c1]) * s_state[c1];
        rhi += lrelu(acc[nt * 4 + 2] + s_cb[c0]) * s_state[c0]
             + lrelu(acc[nt * 4 + 3] + s_cb[c1]) * s_state[c1];
    }
    rlo += __shfl_xor_sync(0xFFFFFFFFu, rlo, 1);
    rlo += __shfl_xor_sync(0xFFFFFFFFu, rlo, 2);
    rhi += __shfl_xor_sync(0xFFFFFFFFu, rhi, 1);
    rhi += __shfl_xor_sync(0xFFFFFFFFu, rhi, 2);

    if ((lane & 3) == 0) {
        const float scale = 0.08838834764831845f;   // 1/sqrt(128)
        int row0 = wrow + l4;
        int rr = rr0 + row0;
        out[b * (MN_ + 1) + (rr & 255)] = cmask[rr] ? rlo * scale : -100000.f;
        rr = rr0 + row0 + 8;
        out[b * (MN_ + 1) + (rr & 255)] = cmask[rr] ? rhi * scale : -100000.f;
    }
}

// ============================================================================
// launch
// ============================================================================
extern "C" void kernel_launch(void* const* d_in, const int* in_sizes, int n_in,
                              void* d_out, int out_size)
{
    const int*   start_entities      = (const int*)  d_in[0];
    const int*   aims                = (const int*)  d_in[1];
    /* node_pos = d_in[2]: arange(1..K), folded into indexing */
    const int*   neighbor_nodes      = (const int*)  d_in[3];
    const int*   neighbor_relations  = (const int*)  d_in[4];
    const int*   neighbors_num       = (const int*)  d_in[5];
    const int*   currents            = (const int*)  d_in[6];
    const int*   candidate_nodes     = (const int*)  d_in[7];
    const int*   candidate_entities  = (const int*)  d_in[8];
    const int*   candidate_relations = (const int*)  d_in[9];
    const int*   candidate_masks     = (const int*)  d_in[10];   // bool -> int32
    const float* entity_emb          = (const float*)d_in[11];
    const float* relation_emb        = (const float*)d_in[12];
    const float* hidden_W            = (const float*)d_in[13];
    const float* hidden_b            = (const float*)d_in[14];
    const float* pass_W              = (const float*)d_in[15];
    const float* pass_b              = (const float*)d_in[16];
    const float* nexthop_W           = (const float*)d_in[17];
    const float* nexthop_b           = (const float*)d_in[18];
    const float* candidate_W         = (const float*)d_in[19];
    const float* candidate_b         = (const float*)d_in[20];
    const float* gate_W              = (const float*)d_in[21];
    const float* gate_b              = (const float*)d_in[22];
    const float* query               = (const float*)d_in[23];
    float* out = (float*)d_out;

    kprep_cw <<<192, 256>>>(candidate_W);
    k1_init  <<<B_, 128>>>(start_entities, entity_emb, hidden_W, hidden_b, pass_W);
    k2_relsum<<<B_ * K_, 128>>>(neighbor_nodes, neighbor_relations, neighbors_num, relation_emb);
    k3_upd   <<<(B_ * K_) / BM3, 256>>>(aims, entity_emb, hidden_W, pass_W, hidden_b, pass_b);
    k4a_cc   <<<B_, 128>>>(currents, query, gate_W, gate_b, out);
    k4t_trans<<<128, 256>>>(nexthop_W);
    k4c_state<<<B_, 128>>>(nexthop_b);
    k5_cand  <<<(B_ * MN_) / 128, 256>>>(candidate_nodes, candidate_entities,
                                         candidate_relations, candidate_masks,
                                         entity_emb, relation_emb, candidate_b, out);
}

// round 5
// speedup vs baseline: 2.7069x; 1.3279x over previous
#include <cuda_runtime.h>
#include <cuda_bf16.h>
#include <cstdint>

// ---------------- problem constants ----------------
#define B_   256
#define K_   32
#define M_   64
#define MN_  256
#define E_   128
#define H_   128
#define Q_   128

// ---------------- scratch (device globals) ----------------
__device__ float g_init  [B_ * H_];
__device__ float g_pnode [B_ * H_];
__device__ float g_relsum[B_ * K_ * E_];
__device__ float g_c0d   [B_ * K_];
__device__ float g_cd    [B_ * K_];
__device__ float g_upd   [B_ * K_ * H_];
__device__ float g_state [B_ * H_];
__device__ float g_cc    [B_ * (H_ + Q_)];
__device__ float g_nWT   [(H_ + Q_) * H_];        // nexthop_W transposed
__device__ float g_zero  [H_];                    // stays zero
__device__ __nv_bfloat16 g_cWb [H_ * 384];        // candidate_W in bf16
__device__ __nv_bfloat16 g_hpWb[H_ * 256];        // [hidden_W | pass_W[:,128:]] bf16

__device__ __forceinline__ float lrelu(float x) { return x >= 0.f ? x : 0.01f * x; }

// warp-level bf16 tensor-core mma (sm_80+ baseline PTX -> HMMA on Blackwell)
__device__ __forceinline__ void mma16816(float* c, const uint32_t* a, const uint32_t* b) {
    asm volatile(
        "mma.sync.aligned.m16n8k16.row.col.f32.bf16.bf16.f32 "
        "{%0,%1,%2,%3}, {%4,%5,%6,%7}, {%8,%9}, {%0,%1,%2,%3};"
        : "+f"(c[0]), "+f"(c[1]), "+f"(c[2]), "+f"(c[3])
        : "r"(a[0]), "r"(a[1]), "r"(a[2]), "r"(a[3]), "r"(b[0]), "r"(b[1]));
}

__device__ __forceinline__ uint4 cvt8_bf16(float4 va, float4 vb) {
    __nv_bfloat162 p0 = __floats2bfloat162_rn(va.x, va.y);
    __nv_bfloat162 p1 = __floats2bfloat162_rn(va.z, va.w);
    __nv_bfloat162 p2 = __floats2bfloat162_rn(vb.x, vb.y);
    __nv_bfloat162 p3 = __floats2bfloat162_rn(vb.z, vb.w);
    uint4 u;
    u.x = *(uint32_t*)&p0; u.y = *(uint32_t*)&p1;
    u.z = *(uint32_t*)&p2; u.w = *(uint32_t*)&p3;
    return u;
}

// ============================================================================
// Kernel P: one-shot weight prep
//   [0, 49152)          candidate_W -> bf16
//   [49152, 81920)      [hidden_W | pass_W[:,128:]] -> bf16
//   [81920, 114688)     nexthop_W transpose (fp32)
// ============================================================================
__global__ void kprep(const float* __restrict__ cW, const float* __restrict__ hW,
                      const float* __restrict__ pW, const float* __restrict__ nW)
{
    int i = blockIdx.x * 256 + threadIdx.x;
    if (i < 49152) {
        g_cWb[i] = __float2bfloat16(cW[i]);
    } else if (i < 81920) {
        int j = i - 49152;
        int n = j >> 8, k = j & 255;
        g_hpWb[j] = __float2bfloat16(k < 128 ? hW[n * 128 + k] : pW[n * 256 + k]);
    } else if (i < 114688) {
        int m = i - 81920;
        int e = m >> 7, n = m & 127;
        g_nWT[m] = nW[n * 256 + e];
    }
}

// ============================================================================
// Kernel 1: init + pnode
// ============================================================================
__global__ void k1_init(const int* __restrict__ start, const float* __restrict__ ent,
                        const float* __restrict__ hW, const float* __restrict__ hb,
                        const float* __restrict__ pW)
{
    int b = blockIdx.x, t = threadIdx.x;
    __shared__ float xs[E_], iv[H_];
    xs[t] = ent[(long)start[b] * E_ + t];
    __syncthreads();
    float acc = 0.f;
    const float* wr = hW + t * E_;
    #pragma unroll 8
    for (int e = 0; e < E_; e++) acc += wr[e] * xs[e];
    float v = lrelu(acc + hb[t]);
    iv[t] = v;
    g_init[b * H_ + t] = v;
    __syncthreads();
    float p = 0.f;
    const float* pr = pW + t * (H_ + E_);
    #pragma unroll 8
    for (int e = 0; e < H_; e++) p += pr[e] * iv[e];
    g_pnode[b * H_ + t] = p;
}

// ============================================================================
// Kernel 2: relsum / counts
// ============================================================================
__global__ void k2_relsum(const int* __restrict__ nb_nodes, const int* __restrict__ nb_rels,
                          const int* __restrict__ nb_num, const float* __restrict__ rel_emb)
{
    int r = blockIdx.x, t = threadIdx.x;
    __shared__ int s_rel[M_];
    __shared__ int s_c0;
    if (t == 0) s_c0 = 0;
    int cnt = nb_num[r];
    if (cnt < 0)  cnt = 0;
    if (cnt > M_) cnt = M_;
    if (t < M_) s_rel[t] = nb_rels[r * M_ + t];
    __syncthreads();
    if (t < cnt && nb_nodes[r * M_ + t] == 0) atomicAdd(&s_c0, 1);
    float acc = 0.f;
    for (int m = 0; m < cnt; m++) acc += rel_emb[s_rel[m] * E_ + t];
    __syncthreads();
    float denom = (cnt == 0) ? 1.f : (float)cnt;
    g_relsum[r * E_ + t] = acc / denom;
    if (t == 0) { g_c0d[r] = (float)s_c0 / denom; g_cd[r] = (float)cnt / denom; }
}

#define PITCH 72   // 64 bf16 + 8 pad; conflict-free for STS.128 and frag LDS

// ============================================================================
// Kernel 3 (warp-mma bf16): upd GEMM  R=8192, N=128, K=256 (4 tiles of 64)
//   grid(64), block(256); software-pipelined global->reg prefetch
// ============================================================================
__global__ __launch_bounds__(256)
void k3_upd(const int* __restrict__ aims, const float* __restrict__ ent,
            const float* __restrict__ hb, const float* __restrict__ pb)
{
    __shared__ __nv_bfloat16 As[128 * PITCH];
    __shared__ __nv_bfloat16 Bs[128 * PITCH];
    __shared__ const float* rowp[128];
    __shared__ float s_c0d[128], s_cd[128], s_hb[128], s_pb[128], s_pn[4 * 128];

    int t    = threadIdx.x;
    int wid  = t >> 5, lane = t & 31;
    int l4   = lane >> 2, lp2 = (lane & 3) * 2;
    int wrow = wid * 16;
    int rr0  = blockIdx.x * 128;
    int b0   = rr0 >> 5;                  // first of 4 batch rows in this CTA

    if (t < 128) {
        int rr = rr0 + t;
        rowp[t]  = ent + (long)aims[rr] * E_;
        s_c0d[t] = g_c0d[rr];
        s_cd[t]  = g_cd[rr];
        s_hb[t]  = hb[t];
        s_pb[t]  = pb[t];
    }
    #pragma unroll
    for (int i = 0; i < 2; i++) {
        int idx = t + i * 256;
        s_pn[idx] = g_pnode[b0 * H_ + idx];
    }
    __syncthreads();

    float acc[64];
    #pragma unroll
    for (int i = 0; i < 64; i++) acc[i] = 0.f;

    uint4 aPf[4], bPf[4];
    // prefetch tile 0
    {
        const int j = 0;
        #pragma unroll
        for (int i = 0; i < 4; i++) {
            int id = t + i * 256;
            int row = id >> 3, c0 = (id & 7) * 8;
            const float* src = rowp[row] + c0;            // seg 0, kof 0
            aPf[i] = cvt8_bf16(*(const float4*)src, *(const float4*)(src + 4));
            bPf[i] = *(const uint4*)(g_hpWb + row * 256 + j * 64 + c0);
        }
    }

    #pragma unroll
    for (int j = 0; j < 4; j++) {
        // commit prefetched tile j to smem
        #pragma unroll
        for (int i = 0; i < 4; i++) {
            int id = t + i * 256;
            int row = id >> 3, c0 = (id & 7) * 8;
            *(uint4*)(As + row * PITCH + c0) = aPf[i];
            *(uint4*)(Bs + row * PITCH + c0) = bPf[i];
        }
        __syncthreads();

        // prefetch tile j+1 (overlaps with mma below)
        if (j < 3) {
            int jn = j + 1;
            int seg = jn >> 1, kof = (jn & 1) * 64;
            #pragma unroll
            for (int i = 0; i < 4; i++) {
                int id = t + i * 256;
                int row = id >> 3, c0 = (id & 7) * 8;
                const float* src = (seg == 0) ? (rowp[row] + kof + c0)
                                              : (g_relsum + (rr0 + row) * E_ + kof + c0);
                aPf[i] = cvt8_bf16(*(const float4*)src, *(const float4*)(src + 4));
                bPf[i] = *(const uint4*)(g_hpWb + row * 256 + jn * 64 + c0);
            }
        }

        #pragma unroll
        for (int ks = 0; ks < 4; ks++) {
            int k0 = ks * 16;
            uint32_t a[4];
            a[0] = *(const uint32_t*)(As + (wrow + l4)     * PITCH + k0 + lp2);
            a[1] = *(const uint32_t*)(As + (wrow + l4 + 8) * PITCH + k0 + lp2);
            a[2] = *(const uint32_t*)(As + (wrow + l4)     * PITCH + k0 + lp2 + 8);
            a[3] = *(const uint32_t*)(As + (wrow + l4 + 8) * PITCH + k0 + lp2 + 8);
            #pragma unroll
            for (int nt = 0; nt < 16; nt++) {
                uint32_t bb[2];
                bb[0] = *(const uint32_t*)(Bs + (nt * 8 + l4) * PITCH + k0 + lp2);
                bb[1] = *(const uint32_t*)(Bs + (nt * 8 + l4) * PITCH + k0 + lp2 + 8);
                mma16816(acc + nt * 4, a, bb);
            }
        }
        __syncthreads();
    }

    // epilogue: v = acc + hb + c0d*pnode + cd*pb; lrelu -> g_upd
    int r0 = wrow + l4, r1 = r0 + 8;
    int bi0 = r0 >> 5, bi1 = r1 >> 5;
    #pragma unroll
    for (int nt = 0; nt < 16; nt++) {
        int c0 = nt * 8 + lp2, c1 = c0 + 1;
        g_upd[(rr0 + r0) * H_ + c0] =
            lrelu(acc[nt*4+0] + s_hb[c0] + s_c0d[r0] * s_pn[bi0 * 128 + c0] + s_cd[r0] * s_pb[c0]);
        g_upd[(rr0 + r0) * H_ + c1] =
            lrelu(acc[nt*4+1] + s_hb[c1] + s_c0d[r0] * s_pn[bi0 * 128 + c1] + s_cd[r0] * s_pb[c1]);
        g_upd[(rr0 + r1) * H_ + c0] =
            lrelu(acc[nt*4+2] + s_hb[c0] + s_c0d[r1] * s_pn[bi1 * 128 + c0] + s_cd[r1] * s_pb[c0]);
        g_upd[(rr0 + r1) * H_ + c1] =
            lrelu(acc[nt*4+3] + s_hb[c1] + s_c0d[r1] * s_pn[bi1 * 128 + c1] + s_cd[r1] * s_pb[c1]);
    }
}

// ============================================================================
// Kernel 4a: build cc[b] = [cur ; query], gate -> out[:, MN]
// ============================================================================
__global__ void k4a_cc(const int* __restrict__ currents, const float* __restrict__ query,
                       const float* __restrict__ gW, const float* __restrict__ gb,
                       float* __restrict__ out)
{
    int b = blockIdx.x, t = threadIdx.x;
    __shared__ float red[128];
    int c = currents[b];
    float cur;
    if (c == 0)                 cur = g_init[b * H_ + t];
    else if (c >= 1 && c <= K_) cur = g_upd[(b * K_ + (c - 1)) * H_ + t];
    else                        cur = 0.f;
    float q = query[b * Q_ + t];
    g_cc[b * 256 + t]       = cur;
    g_cc[b * 256 + 128 + t] = q;
    red[t] = gW[t] * cur + gW[128 + t] * q;
    __syncthreads();
    for (int s = 64; s > 0; s >>= 1) {
        if (t < s) red[t] += red[t + s];
        __syncthreads();
    }
    if (t == 0) out[b * (MN_ + 1) + MN_] = red[0] + gb[0];
}

// ============================================================================
// Kernel 4c: state[b][n] = lrelu( sum_e cc[b][e] * nWT[e][n] + nbias[n] )
// ============================================================================
__global__ void k4c_state(const float* __restrict__ nbias)
{
    int b = blockIdx.x, n = threadIdx.x;
    __shared__ float s_cc[256];
    s_cc[n] = g_cc[b * 256 + n];
    s_cc[128 + n] = g_cc[b * 256 + 128 + n];
    __syncthreads();
    float acc = 0.f;
    #pragma unroll 8
    for (int e = 0; e < 256; e++) acc += s_cc[e] * g_nWT[e * 128 + n];
    g_state[b * H_ + n] = lrelu(acc + nbias[n]);
}

// ============================================================================
// Kernel 5: warp-mma bf16 candidate GEMM + fused epilogue (pipelined)
//   per CTA: M=128 gathered rows, N=128, K=384 (6 tiles of 64); grid(512)
// ============================================================================
__global__ __launch_bounds__(256)
void k5_cand(const int* __restrict__ cnodes, const int* __restrict__ cents,
             const int* __restrict__ crels, const int* __restrict__ cmask,
             const float* __restrict__ ent, const float* __restrict__ rel,
             const float* __restrict__ cb, float* __restrict__ out)
{
    __shared__ __nv_bfloat16 As[128 * PITCH];
    __shared__ __nv_bfloat16 Bs[128 * PITCH];
    __shared__ const float* pN[128];
    __shared__ const float* pE[128];
    __shared__ const float* pR[128];
    __shared__ float s_state[H_], s_cb[H_];

    int t    = threadIdx.x;
    int wid  = t >> 5, lane = t & 31;
    int l4   = lane >> 2, lp2 = (lane & 3) * 2;
    int wrow = wid * 16;
    int rr0  = blockIdx.x * 128;
    int b    = rr0 >> 8;

    if (t < 128) {
        int rr = rr0 + t;
        int node = cnodes[rr];
        const float* p;
        if (node == 0)                    p = g_init + b * H_;
        else if (node >= 1 && node <= K_) p = g_upd + (b * K_ + (node - 1)) * H_;
        else                              p = g_zero;
        pN[t] = p;
        pE[t] = ent + (long)cents[rr] * E_;
        pR[t] = rel + (long)crels[rr] * E_;
        s_state[t] = g_state[b * H_ + t];
        s_cb[t]    = cb[t];
    }
    __syncthreads();

    float acc[64];
    #pragma unroll
    for (int i = 0; i < 64; i++) acc[i] = 0.f;

    uint4 aPf[4], bPf[4];
    // prefetch tile 0
    #pragma unroll
    for (int i = 0; i < 4; i++) {
        int id = t + i * 256;
        int row = id >> 3, c0 = (id & 7) * 8;
        const float* src = pN[row] + c0;
        aPf[i] = cvt8_bf16(*(const float4*)src, *(const float4*)(src + 4));
        bPf[i] = *(const uint4*)(g_cWb + row * 384 + c0);
    }

    #pragma unroll
    for (int j = 0; j < 6; j++) {
        #pragma unroll
        for (int i = 0; i < 4; i++) {
            int id = t + i * 256;
            int row = id >> 3, c0 = (id & 7) * 8;
            *(uint4*)(As + row * PITCH + c0) = aPf[i];
            *(uint4*)(Bs + row * PITCH + c0) = bPf[i];
        }
        __syncthreads();

        if (j < 5) {
            int jn = j + 1;
            int seg = jn >> 1, kof = (jn & 1) * 64;
            const float* const* ptab = (seg == 0) ? pN : (seg == 1) ? pE : pR;
            #pragma unroll
            for (int i = 0; i < 4; i++) {
                int id = t + i * 256;
                int row = id >> 3, c0 = (id & 7) * 8;
                const float* src = ptab[row] + kof + c0;
                aPf[i] = cvt8_bf16(*(const float4*)src, *(const float4*)(src + 4));
                bPf[i] = *(const uint4*)(g_cWb + row * 384 + jn * 64 + c0);
            }
        }

        #pragma unroll
        for (int ks = 0; ks < 4; ks++) {
            int k0 = ks * 16;
            uint32_t a[4];
            a[0] = *(const uint32_t*)(As + (wrow + l4)     * PITCH + k0 + lp2);
            a[1] = *(const uint32_t*)(As + (wrow + l4 + 8) * PITCH + k0 + lp2);
            a[2] = *(const uint32_t*)(As + (wrow + l4)     * PITCH + k0 + lp2 + 8);
            a[3] = *(const uint32_t*)(As + (wrow + l4 + 8) * PITCH + k0 + lp2 + 8);
            #pragma unroll
            for (int nt = 0; nt < 16; nt++) {
                uint32_t bb[2];
                bb[0] = *(const uint32_t*)(Bs + (nt * 8 + l4) * PITCH + k0 + lp2);
                bb[1] = *(const uint32_t*)(Bs + (nt * 8 + l4) * PITCH + k0 + lp2 + 8);
                mma16816(acc + nt * 4, a, bb);
            }
        }
        __syncthreads();
    }

    // epilogue: lrelu+bias, dot(state); reduce quad
    float rlo = 0.f, rhi = 0.f;
    #pragma unroll
    for (int nt = 0; nt < 16; nt++) {
        int c0 = nt * 8 + lp2, c1 = c0 + 1;
        rlo += lrelu(acc[nt * 4 + 0] + s_cb[c0]) * s_state[c0]
             + lrelu(acc[nt * 4 + 1] + s_cb[c1]) * s_state[c1];
        rhi += lrelu(acc[nt * 4 + 2] + s_cb[c0]) * s_state[c0]
             + lrelu(acc[nt * 4 + 3] + s_cb[c1]) * s_state[c1];
    }
    rlo += __shfl_xor_sync(0xFFFFFFFFu, rlo, 1);
    rlo += __shfl_xor_sync(0xFFFFFFFFu, rlo, 2);
    rhi += __shfl_xor_sync(0xFFFFFFFFu, rhi, 1);
    rhi += __shfl_xor_sync(0xFFFFFFFFu, rhi, 2);

    if ((lane & 3) == 0) {
        const float scale = 0.08838834764831845f;   // 1/sqrt(128)
        int row0 = wrow + l4;
        int rr = rr0 + row0;
        out[b * (MN_ + 1) + (rr & 255)] = cmask[rr] ? rlo * scale : -100000.f;
        rr = rr0 + row0 + 8;
        out[b * (MN_ + 1) + (rr & 255)] = cmask[rr] ? rhi * scale : -100000.f;
    }
}

// ============================================================================
// launch
// ============================================================================
extern "C" void kernel_launch(void* const* d_in, const int* in_sizes, int n_in,
                              void* d_out, int out_size)
{
    const int*   start_entities      = (const int*)  d_in[0];
    const int*   aims                = (const int*)  d_in[1];
    /* node_pos = d_in[2]: arange(1..K), folded into indexing */
    const int*   neighbor_nodes      = (const int*)  d_in[3];
    const int*   neighbor_relations  = (const int*)  d_in[4];
    const int*   neighbors_num       = (const int*)  d_in[5];
    const int*   currents            = (const int*)  d_in[6];
    const int*   candidate_nodes     = (const int*)  d_in[7];
    const int*   candidate_entities  = (const int*)  d_in[8];
    const int*   candidate_relations = (const int*)  d_in[9];
    const int*   candidate_masks     = (const int*)  d_in[10];   // bool -> int32
    const float* entity_emb          = (const float*)d_in[11];
    const float* relation_emb        = (const float*)d_in[12];
    const float* hidden_W            = (const float*)d_in[13];
    const float* hidden_b            = (const float*)d_in[14];
    const float* pass_W              = (const float*)d_in[15];
    const float* pass_b              = (const float*)d_in[16];
    const float* nexthop_W           = (const float*)d_in[17];
    const float* nexthop_b           = (const float*)d_in[18];
    const float* candidate_W         = (const float*)d_in[19];
    const float* candidate_b         = (const float*)d_in[20];
    const float* gate_W              = (const float*)d_in[21];
    const float* gate_b              = (const float*)d_in[22];
    const float* query               = (const float*)d_in[23];
    float* out = (float*)d_out;

    kprep    <<<448, 256>>>(candidate_W, hidden_W, pass_W, nexthop_W);
    k1_init  <<<B_, 128>>>(start_entities, entity_emb, hidden_W, hidden_b, pass_W);
    k2_relsum<<<B_ * K_, 128>>>(neighbor_nodes, neighbor_relations, neighbors_num, relation_emb);
    k3_upd   <<<64, 256>>>(aims, entity_emb, hidden_b, pass_b);
    k4a_cc   <<<B_, 128>>>(currents, query, gate_W, gate_b, out);
    k4c_state<<<B_, 128>>>(nexthop_b);
    k5_cand  <<<(B_ * MN_) / 128, 256>>>(candidate_nodes, candidate_entities,
                                         candidate_relations, candidate_masks,
                                         entity_emb, relation_emb, candidate_b, out);
}

// round 6
// speedup vs baseline: 2.8448x; 1.0510x over previous
#include <cuda_runtime.h>
#include <cuda_bf16.h>
#include <cstdint>

// ---------------- problem constants ----------------
#define B_   256
#define K_   32
#define M_   64
#define MN_  256
#define E_   128
#define H_   128
#define Q_   128

// ---------------- scratch (device globals) ----------------
__device__ float g_init  [B_ * H_];
__device__ float g_pnode [B_ * H_];
__device__ float g_relsum[B_ * K_ * E_];
__device__ float g_c0d   [B_ * K_];
__device__ float g_cd    [B_ * K_];
__device__ float g_upd   [B_ * K_ * H_];
__device__ float g_state [B_ * H_];
__device__ float g_nWT   [(H_ + Q_) * H_];        // nexthop_W transposed
__device__ float g_zero  [H_];                    // stays zero
__device__ __nv_bfloat16 g_cWb [H_ * 384];        // candidate_W in bf16
__device__ __nv_bfloat16 g_hpWb[H_ * 256];        // [hidden_W | pass_W[:,128:]] bf16

__device__ __forceinline__ float lrelu(float x) { return x >= 0.f ? x : 0.01f * x; }

__device__ __forceinline__ uint32_t smem_u32(const void* p) {
    uint32_t a;
    asm("{ .reg .u64 t; cvta.to.shared.u64 t, %1; cvt.u32.u64 %0, t; }" : "=r"(a) : "l"(p));
    return a;
}

// warp-level bf16 tensor-core mma (sm_80+ baseline PTX -> HMMA on Blackwell)
__device__ __forceinline__ void mma16816(float* c, const uint32_t* a, const uint32_t* b) {
    asm volatile(
        "mma.sync.aligned.m16n8k16.row.col.f32.bf16.bf16.f32 "
        "{%0,%1,%2,%3}, {%4,%5,%6,%7}, {%8,%9}, {%0,%1,%2,%3};"
        : "+f"(c[0]), "+f"(c[1]), "+f"(c[2]), "+f"(c[3])
        : "r"(a[0]), "r"(a[1]), "r"(a[2]), "r"(a[3]), "r"(b[0]), "r"(b[1]));
}
__device__ __forceinline__ void ldm_x4(uint32_t* r, uint32_t addr) {
    asm volatile("ldmatrix.sync.aligned.m8n8.x4.shared.b16 {%0,%1,%2,%3}, [%4];"
        : "=r"(r[0]), "=r"(r[1]), "=r"(r[2]), "=r"(r[3]) : "r"(addr));
}

__device__ __forceinline__ uint4 cvt8_bf16(float4 va, float4 vb) {
    __nv_bfloat162 p0 = __floats2bfloat162_rn(va.x, va.y);
    __nv_bfloat162 p1 = __floats2bfloat162_rn(va.z, va.w);
    __nv_bfloat162 p2 = __floats2bfloat162_rn(vb.x, vb.y);
    __nv_bfloat162 p3 = __floats2bfloat162_rn(vb.z, vb.w);
    uint4 u;
    u.x = *(uint32_t*)&p0; u.y = *(uint32_t*)&p1;
    u.z = *(uint32_t*)&p2; u.w = *(uint32_t*)&p3;
    return u;
}

#define PITCH 72   // 64 bf16 + 8 pad: ldmatrix rows land on distinct banks

// ============================================================================
// Kernel P: one-shot weight prep
// ============================================================================
__global__ void kprep(const float* __restrict__ cW, const float* __restrict__ hW,
                      const float* __restrict__ pW, const float* __restrict__ nW)
{
    int i = blockIdx.x * 256 + threadIdx.x;
    if (i < 49152) {
        g_cWb[i] = __float2bfloat16(cW[i]);
    } else if (i < 81920) {
        int j = i - 49152;
        int n = j >> 8, k = j & 255;
        g_hpWb[j] = __float2bfloat16(k < 128 ? hW[n * 128 + k] : pW[n * 256 + k]);
    } else if (i < 114688) {
        int m = i - 81920;
        int e = m >> 7, n = m & 127;
        g_nWT[m] = nW[n * 256 + e];
    }
}

// ============================================================================
// Kernel 1: init + pnode
// ============================================================================
__global__ void k1_init(const int* __restrict__ start, const float* __restrict__ ent,
                        const float* __restrict__ hW, const float* __restrict__ hb,
                        const float* __restrict__ pW)
{
    int b = blockIdx.x, t = threadIdx.x;
    __shared__ float xs[E_], iv[H_];
    xs[t] = ent[(long)start[b] * E_ + t];
    __syncthreads();
    float acc = 0.f;
    const float* wr = hW + t * E_;
    #pragma unroll 8
    for (int e = 0; e < E_; e++) acc += wr[e] * xs[e];
    float v = lrelu(acc + hb[t]);
    iv[t] = v;
    g_init[b * H_ + t] = v;
    __syncthreads();
    float p = 0.f;
    const float* pr = pW + t * (H_ + E_);
    #pragma unroll 8
    for (int e = 0; e < H_; e++) p += pr[e] * iv[e];
    g_pnode[b * H_ + t] = p;
}

// ============================================================================
// Kernel 2: relsum / counts
// ============================================================================
__global__ void k2_relsum(const int* __restrict__ nb_nodes, const int* __restrict__ nb_rels,
                          const int* __restrict__ nb_num, const float* __restrict__ rel_emb)
{
    int r = blockIdx.x, t = threadIdx.x;
    __shared__ int s_rel[M_];
    __shared__ int s_c0;
    if (t == 0) s_c0 = 0;
    int cnt = nb_num[r];
    if (cnt < 0)  cnt = 0;
    if (cnt > M_) cnt = M_;
    if (t < M_) s_rel[t] = nb_rels[r * M_ + t];
    __syncthreads();
    if (t < cnt && nb_nodes[r * M_ + t] == 0) atomicAdd(&s_c0, 1);
    float acc = 0.f;
    for (int m = 0; m < cnt; m++) acc += rel_emb[s_rel[m] * E_ + t];
    __syncthreads();
    float denom = (cnt == 0) ? 1.f : (float)cnt;
    g_relsum[r * E_ + t] = acc / denom;
    if (t == 0) { g_c0d[r] = (float)s_c0 / denom; g_cd[r] = (float)cnt / denom; }
}

// ============================================================================
// Kernel 3 (warp-mma bf16 + ldmatrix): upd GEMM  R=8192, N=128, K=256
//   BM=64, grid(128), block(256): 8 warps = 4 M-slices x 2 N-halves, acc[32]
// ============================================================================
__global__ __launch_bounds__(256)
void k3_upd(const int* __restrict__ aims, const float* __restrict__ ent,
            const float* __restrict__ hb, const float* __restrict__ pb)
{
    __shared__ __nv_bfloat16 As[64 * PITCH];     //  9216 B
    __shared__ __nv_bfloat16 Bs[128 * PITCH];    // 18432 B
    __shared__ const float* rowp[64];
    __shared__ float s_c0d[64], s_cd[64], s_hb[128], s_pb[128], s_pn[2 * 128];

    int t    = threadIdx.x;
    int wid  = t >> 5, lane = t & 31;
    int l4   = lane >> 2, lp2 = (lane & 3) * 2;
    int wrow = (wid & 3) * 16;
    int nb8  = (wid >> 2) * 8;                   // warp's first n-tile
    int rr0  = blockIdx.x * 64;
    int b0   = rr0 >> 5;

    if (t < 64) {
        int rr = rr0 + t;
        rowp[t]  = ent + (long)aims[rr] * E_;
        s_c0d[t] = g_c0d[rr];
        s_cd[t]  = g_cd[rr];
    }
    if (t < 128) {
        s_hb[t] = hb[t];
        s_pb[t] = pb[t];
        s_pn[t] = g_pnode[b0 * H_ + t];
        s_pn[128 + t] = g_pnode[(b0 + 1) * H_ + t];
    }
    __syncthreads();

    uint32_t asb = smem_u32(As), bsb = smem_u32(Bs);
    uint32_t a_off = (uint32_t)((wrow + (lane & 15)) * PITCH + ((lane >> 4) << 3)) * 2;
    uint32_t b_off = (uint32_t)((nb8 * 8 + (lane & 7) + ((lane >> 4) << 3)) * PITCH
                                + (((lane >> 3) & 1) << 3)) * 2;

    float acc[32];
    #pragma unroll
    for (int i = 0; i < 32; i++) acc[i] = 0.f;

    uint4 aPf[2], bPf[4];
    // prefetch tile 0 (A: 64x64 -> 512 chunks/256t = 2; B: 128x64 -> 4)
    #pragma unroll
    for (int i = 0; i < 2; i++) {
        int id = t + i * 256;
        int row = id >> 3, c0 = (id & 7) * 8;
        const float* src = rowp[row] + c0;
        aPf[i] = cvt8_bf16(*(const float4*)src, *(const float4*)(src + 4));
    }
    #pragma unroll
    for (int i = 0; i < 4; i++) {
        int id = t + i * 256;
        int row = id >> 3, c0 = (id & 7) * 8;
        bPf[i] = *(const uint4*)(g_hpWb + row * 256 + c0);
    }

    #pragma unroll
    for (int j = 0; j < 4; j++) {
        #pragma unroll
        for (int i = 0; i < 2; i++) {
            int id = t + i * 256;
            int row = id >> 3, c0 = (id & 7) * 8;
            *(uint4*)(As + row * PITCH + c0) = aPf[i];
        }
        #pragma unroll
        for (int i = 0; i < 4; i++) {
            int id = t + i * 256;
            int row = id >> 3, c0 = (id & 7) * 8;
            *(uint4*)(Bs + row * PITCH + c0) = bPf[i];
        }
        __syncthreads();

        if (j < 3) {
            int jn = j + 1;
            int kof = (jn & 1) * 64;
            #pragma unroll
            for (int i = 0; i < 2; i++) {
                int id = t + i * 256;
                int row = id >> 3, c0 = (id & 7) * 8;
                const float* src = (jn < 2) ? (rowp[row] + kof + c0)
                                            : (g_relsum + (rr0 + row) * E_ + kof + c0);
                aPf[i] = cvt8_bf16(*(const float4*)src, *(const float4*)(src + 4));
            }
            #pragma unroll
            for (int i = 0; i < 4; i++) {
                int id = t + i * 256;
                int row = id >> 3, c0 = (id & 7) * 8;
                bPf[i] = *(const uint4*)(g_hpWb + row * 256 + jn * 64 + c0);
            }
        }

        #pragma unroll
        for (int ks = 0; ks < 4; ks++) {
            uint32_t kb = (uint32_t)(ks * 16) * 2;
            uint32_t a[4];
            ldm_x4(a, asb + a_off + kb);
            #pragma unroll
            for (int p = 0; p < 4; p++) {
                uint32_t bq[4];
                ldm_x4(bq, bsb + b_off + (uint32_t)(p * 16 * PITCH) * 2 + kb);
                mma16816(acc + (p * 2) * 4,     a, bq);
                mma16816(acc + (p * 2 + 1) * 4, a, bq + 2);
            }
        }
        __syncthreads();
    }

    // epilogue -> g_upd
    int r0 = wrow + l4, r1 = r0 + 8;
    int bi0 = (r0 >> 5) * 128, bi1 = (r1 >> 5) * 128;
    #pragma unroll
    for (int p2 = 0; p2 < 8; p2++) {
        int c0 = (nb8 + p2) * 8 + lp2, c1 = c0 + 1;
        g_upd[(rr0 + r0) * H_ + c0] =
            lrelu(acc[p2*4+0] + s_hb[c0] + s_c0d[r0] * s_pn[bi0 + c0] + s_cd[r0] * s_pb[c0]);
        g_upd[(rr0 + r0) * H_ + c1] =
            lrelu(acc[p2*4+1] + s_hb[c1] + s_c0d[r0] * s_pn[bi0 + c1] + s_cd[r0] * s_pb[c1]);
        g_upd[(rr0 + r1) * H_ + c0] =
            lrelu(acc[p2*4+2] + s_hb[c0] + s_c0d[r1] * s_pn[bi1 + c0] + s_cd[r1] * s_pb[c0]);
        g_upd[(rr0 + r1) * H_ + c1] =
            lrelu(acc[p2*4+3] + s_hb[c1] + s_c0d[r1] * s_pn[bi1 + c1] + s_cd[r1] * s_pb[c1]);
    }
}

// ============================================================================
// Kernel 4 (fused): cc = [cur;query]; gate -> out[:,MN]; state matvec
// ============================================================================
__global__ void k4_state(const int* __restrict__ currents, const float* __restrict__ query,
                         const float* __restrict__ gW, const float* __restrict__ gb,
                         const float* __restrict__ nbias, float* __restrict__ out)
{
    int b = blockIdx.x, t = threadIdx.x;
    __shared__ float cc[256];
    __shared__ float red[128];
    int c = currents[b];
    float cur;
    if (c == 0)                 cur = g_init[b * H_ + t];
    else if (c >= 1 && c <= K_) cur = g_upd[(b * K_ + (c - 1)) * H_ + t];
    else                        cur = 0.f;
    float q = query[b * Q_ + t];
    cc[t]       = cur;
    cc[128 + t] = q;
    red[t] = gW[t] * cur + gW[128 + t] * q;
    __syncthreads();
    for (int s = 64; s > 0; s >>= 1) {
        if (t < s) red[t] += red[t + s];
        __syncthreads();
    }
    if (t == 0) out[b * (MN_ + 1) + MN_] = red[0] + gb[0];

    float acc = 0.f;
    #pragma unroll 8
    for (int e = 0; e < 256; e++) acc += cc[e] * g_nWT[e * 128 + t];
    g_state[b * H_ + t] = lrelu(acc + nbias[t]);
}

// ============================================================================
// Kernel 5: warp-mma bf16 + ldmatrix candidate GEMM + fused epilogue
//   BM=128, grid(512), block(512): 16 warps = 8 M-slices x 2 N-halves, acc[32]
// ============================================================================
__global__ __launch_bounds__(512)
void k5_cand(const int* __restrict__ cnodes, const int* __restrict__ cents,
             const int* __restrict__ crels, const int* __restrict__ cmask,
             const float* __restrict__ ent, const float* __restrict__ rel,
             const float* __restrict__ cb, float* __restrict__ out)
{
    __shared__ __nv_bfloat16 As[128 * PITCH];    // 18432 B
    __shared__ __nv_bfloat16 Bs[128 * PITCH];    // 18432 B
    __shared__ const float* pN[128];
    __shared__ const float* pE[128];
    __shared__ const float* pR[128];
    __shared__ float s_state[H_], s_cb[H_];
    __shared__ float sred[16][16];

    int t    = threadIdx.x;
    int wid  = t >> 5, lane = t & 31;
    int l4   = lane >> 2, lp2 = (lane & 3) * 2;
    int wrow = (wid & 7) * 16;
    int nb8  = (wid >> 3) * 8;
    int rr0  = blockIdx.x * 128;
    int b    = rr0 >> 8;

    if (t < 128) {
        int rr = rr0 + t;
        int node = cnodes[rr];
        const float* p;
        if (node == 0)                    p = g_init + b * H_;
        else if (node >= 1 && node <= K_) p = g_upd + (b * K_ + (node - 1)) * H_;
        else                              p = g_zero;
        pN[t] = p;
        pE[t] = ent + (long)cents[rr] * E_;
        pR[t] = rel + (long)crels[rr] * E_;
        s_state[t] = g_state[b * H_ + t];
        s_cb[t]    = cb[t];
    }
    __syncthreads();

    uint32_t asb = smem_u32(As), bsb = smem_u32(Bs);
    uint32_t a_off = (uint32_t)((wrow + (lane & 15)) * PITCH + ((lane >> 4) << 3)) * 2;
    uint32_t b_off = (uint32_t)((nb8 * 8 + (lane & 7) + ((lane >> 4) << 3)) * PITCH
                                + (((lane >> 3) & 1) << 3)) * 2;

    float acc[32];
    #pragma unroll
    for (int i = 0; i < 32; i++) acc[i] = 0.f;

    uint4 aPf[2], bPf[2];
    // prefetch tile 0 (A: 128x64 -> 1024 chunks/512t = 2; B: 2)
    #pragma unroll
    for (int i = 0; i < 2; i++) {
        int id = t + i * 512;
        int row = id >> 3, c0 = (id & 7) * 8;
        const float* src = pN[row] + c0;
        aPf[i] = cvt8_bf16(*(const float4*)src, *(const float4*)(src + 4));
        bPf[i] = *(const uint4*)(g_cWb + row * 384 + c0);
    }

    #pragma unroll
    for (int j = 0; j < 6; j++) {
        #pragma unroll
        for (int i = 0; i < 2; i++) {
            int id = t + i * 512;
            int row = id >> 3, c0 = (id & 7) * 8;
            *(uint4*)(As + row * PITCH + c0) = aPf[i];
            *(uint4*)(Bs + row * PITCH + c0) = bPf[i];
        }
        __syncthreads();

        if (j < 5) {
            int jn = j + 1;
            int seg = jn >> 1, kof = (jn & 1) * 64;
            const float* const* ptab = (seg == 0) ? pN : (seg == 1) ? pE : pR;
            #pragma unroll
            for (int i = 0; i < 2; i++) {
                int id = t + i * 512;
                int row = id >> 3, c0 = (id & 7) * 8;
                const float* src = ptab[row] + kof + c0;
                aPf[i] = cvt8_bf16(*(const float4*)src, *(const float4*)(src + 4));
                bPf[i] = *(const uint4*)(g_cWb + row * 384 + jn * 64 + c0);
            }
        }

        #pragma unroll
        for (int ks = 0; ks < 4; ks++) {
            uint32_t kb = (uint32_t)(ks * 16) * 2;
            uint32_t a[4];
            ldm_x4(a, asb + a_off + kb);
            #pragma unroll
            for (int p = 0; p < 4; p++) {
                uint32_t bq[4];
                ldm_x4(bq, bsb + b_off + (uint32_t)(p * 16 * PITCH) * 2 + kb);
                mma16816(acc + (p * 2) * 4,     a, bq);
                mma16816(acc + (p * 2 + 1) * 4, a, bq + 2);
            }
        }
        __syncthreads();
    }

    // epilogue: lrelu+bias, dot(state), quad-reduce, cross-warp (n-half) reduce
    float rlo = 0.f, rhi = 0.f;
    #pragma unroll
    for (int p2 = 0; p2 < 8; p2++) {
        int c0 = (nb8 + p2) * 8 + lp2, c1 = c0 + 1;
        rlo += lrelu(acc[p2 * 4 + 0] + s_cb[c0]) * s_state[c0]
             + lrelu(acc[p2 * 4 + 1] + s_cb[c1]) * s_state[c1];
        rhi += lrelu(acc[p2 * 4 + 2] + s_cb[c0]) * s_state[c0]
             + lrelu(acc[p2 * 4 + 3] + s_cb[c1]) * s_state[c1];
    }
    rlo += __shfl_xor_sync(0xFFFFFFFFu, rlo, 1);
    rlo += __shfl_xor_sync(0xFFFFFFFFu, rlo, 2);
    rhi += __shfl_xor_sync(0xFFFFFFFFu, rhi, 1);
    rhi += __shfl_xor_sync(0xFFFFFFFFu, rhi, 2);
    if ((lane & 3) == 0) {
        sred[wid][l4]     = rlo;
        sred[wid][l4 + 8] = rhi;
    }
    __syncthreads();

    if (t < 128) {
        int w = t >> 4, r = t & 15;            // M-slice w, row-in-slice r
        float s = (sred[w][r] + sred[w + 8][r]) * 0.08838834764831845f;  // 1/sqrt(128)
        int rr = rr0 + w * 16 + r;
        out[b * (MN_ + 1) + (rr & 255)] = cmask[rr] ? s : -100000.f;
    }
}

// ============================================================================
// launch
// ============================================================================
extern "C" void kernel_launch(void* const* d_in, const int* in_sizes, int n_in,
                              void* d_out, int out_size)
{
    const int*   start_entities      = (const int*)  d_in[0];
    const int*   aims                = (const int*)  d_in[1];
    /* node_pos = d_in[2]: arange(1..K), folded into indexing */
    const int*   neighbor_nodes      = (const int*)  d_in[3];
    const int*   neighbor_relations  = (const int*)  d_in[4];
    const int*   neighbors_num       = (const int*)  d_in[5];
    const int*   currents            = (const int*)  d_in[6];
    const int*   candidate_nodes     = (const int*)  d_in[7];
    const int*   candidate_entities  = (const int*)  d_in[8];
    const int*   candidate_relations = (const int*)  d_in[9];
    const int*   candidate_masks     = (const int*)  d_in[10];   // bool -> int32
    const float* entity_emb          = (const float*)d_in[11];
    const float* relation_emb        = (const float*)d_in[12];
    const float* hidden_W            = (const float*)d_in[13];
    const float* hidden_b            = (const float*)d_in[14];
    const float* pass_W              = (const float*)d_in[15];
    const float* pass_b              = (const float*)d_in[16];
    const float* nexthop_W           = (const float*)d_in[17];
    const float* nexthop_b           = (const float*)d_in[18];
    const float* candidate_W         = (const float*)d_in[19];
    const float* candidate_b         = (const float*)d_in[20];
    const float* gate_W              = (const float*)d_in[21];
    const float* gate_b              = (const float*)d_in[22];
    const float* query               = (const float*)d_in[23];
    float* out = (float*)d_out;

    kprep    <<<448, 256>>>(candidate_W, hidden_W, pass_W, nexthop_W);
    k1_init  <<<B_, 128>>>(start_entities, entity_emb, hidden_W, hidden_b, pass_W);
    k2_relsum<<<B_ * K_, 128>>>(neighbor_nodes, neighbor_relations, neighbors_num, relation_emb);
    k3_upd   <<<128, 256>>>(aims, entity_emb, hidden_b, pass_b);
    k4_state <<<B_, 128>>>(currents, query, gate_W, gate_b, nexthop_b, out);
    k5_cand  <<<(B_ * MN_) / 128, 512>>>(candidate_nodes, candidate_entities,
                                         candidate_relations, candidate_masks,
                                         entity_emb, relation_emb, candidate_b, out);
}

// round 8
// speedup vs baseline: 2.9142x; 1.0244x over previous
#include <cuda_runtime.h>
#include <cuda_bf16.h>
#include <cstdint>

// ---------------- problem constants ----------------
#define B_   256
#define K_   32
#define M_   64
#define MN_  256
#define E_   128
#define H_   128
#define Q_   128

// ---------------- scratch (device globals) ----------------
__device__ float g_init  [B_ * H_];
__device__ float g_pnode [B_ * H_];
__device__ float g_relsum[B_ * K_ * E_];
__device__ float g_c0d   [B_ * K_];
__device__ float g_cd    [B_ * K_];
__device__ float g_upd   [B_ * K_ * H_];
__device__ float g_state [B_ * H_];
__device__ float g_nWT   [(H_ + Q_) * H_];        // nexthop_W transposed
__device__ float g_zero  [H_];                    // stays zero
__device__ __nv_bfloat16 g_cWb [H_ * 384];        // candidate_W in bf16
__device__ __nv_bfloat16 g_hpWb[H_ * 256];        // [hidden_W | pass_W[:,128:]] bf16

__device__ __forceinline__ float lrelu(float x) { return x >= 0.f ? x : 0.01f * x; }

__device__ __forceinline__ uint32_t smem_u32(const void* p) {
    uint32_t a;
    asm("{ .reg .u64 t; cvta.to.shared.u64 t, %1; cvt.u32.u64 %0, t; }" : "=r"(a) : "l"(p));
    return a;
}
__device__ __forceinline__ void mma16816(float* c, const uint32_t* a, const uint32_t* b) {
    asm volatile(
        "mma.sync.aligned.m16n8k16.row.col.f32.bf16.bf16.f32 "
        "{%0,%1,%2,%3}, {%4,%5,%6,%7}, {%8,%9}, {%0,%1,%2,%3};"
        : "+f"(c[0]), "+f"(c[1]), "+f"(c[2]), "+f"(c[3])
        : "r"(a[0]), "r"(a[1]), "r"(a[2]), "r"(a[3]), "r"(b[0]), "r"(b[1]));
}
__device__ __forceinline__ void ldm_x4(uint32_t* r, uint32_t addr) {
    asm volatile("ldmatrix.sync.aligned.m8n8.x4.shared.b16 {%0,%1,%2,%3}, [%4];"
        : "=r"(r[0]), "=r"(r[1]), "=r"(r[2]), "=r"(r[3]) : "r"(addr));
}
__device__ __forceinline__ uint4 cvt8_bf16(float4 va, float4 vb) {
    __nv_bfloat162 p0 = __floats2bfloat162_rn(va.x, va.y);
    __nv_bfloat162 p1 = __floats2bfloat162_rn(va.z, va.w);
    __nv_bfloat162 p2 = __floats2bfloat162_rn(vb.x, vb.y);
    __nv_bfloat162 p3 = __floats2bfloat162_rn(vb.z, vb.w);
    uint4 u;
    u.x = *(uint32_t*)&p0; u.y = *(uint32_t*)&p1;
    u.z = *(uint32_t*)&p2; u.w = *(uint32_t*)&p3;
    return u;
}

#define PITCH2 40   // 32 bf16 + 8 pad: rows at 80B -> distinct banks for ldmatrix

// ============================================================================
// Setup kernel: blocks [0,448) weight prep | [448,704) init/pnode | [704,4800) relsum
// ============================================================================
__global__ __launch_bounds__(256)
void ksetup(const float* __restrict__ cW, const float* __restrict__ hW,
            const float* __restrict__ pW, const float* __restrict__ nW,
            const int* __restrict__ start, const float* __restrict__ ent,
            const float* __restrict__ hb,
            const int* __restrict__ nb_nodes, const int* __restrict__ nb_rels,
            const int* __restrict__ nb_num, const float* __restrict__ rel_emb)
{
    int blk = blockIdx.x, t = threadIdx.x;

    if (blk < 448) {
        // ---- weight prep ----
        int i = blk * 256 + t;
        if (i < 49152) {
            g_cWb[i] = __float2bfloat16(cW[i]);
        } else if (i < 81920) {
            int j = i - 49152;
            int n = j >> 8, k = j & 255;
            g_hpWb[j] = __float2bfloat16(k < 128 ? hW[n * 128 + k] : pW[n * 256 + k]);
        } else {
            int m = i - 81920;
            int e = m >> 7, n = m & 127;
            g_nWT[m] = nW[n * 256 + e];
        }
        return;
    }

    if (blk < 704) {
        // ---- k1: init + pnode (threads 0-127 active) ----
        int b = blk - 448;
        __shared__ float xs[E_], iv[H_];
        if (t < 128) xs[t] = ent[(long)start[b] * E_ + t];
        __syncthreads();
        if (t < 128) {
            float acc = 0.f;
            const float* wr = hW + t * E_;
            #pragma unroll 8
            for (int e = 0; e < E_; e++) acc += wr[e] * xs[e];
            float v = lrelu(acc + hb[t]);
            iv[t] = v;
            g_init[b * H_ + t] = v;
        }
        __syncthreads();
        if (t < 128) {
            float p = 0.f;
            const float* pr = pW + t * (H_ + E_);
            #pragma unroll 8
            for (int e = 0; e < H_; e++) p += pr[e] * iv[e];
            g_pnode[b * H_ + t] = p;
        }
        return;
    }

    // ---- k2: relsum / counts, 2 rows per block ----
    {
        __shared__ int s_rel[2][M_];
        __shared__ int s_c0[2];
        int sub = t >> 7, tt = t & 127;
        int r = (blk - 704) * 2 + sub;
        if (tt == 0) s_c0[sub] = 0;
        int cnt = nb_num[r];
        if (cnt < 0)  cnt = 0;
        if (cnt > M_) cnt = M_;
        if (tt < M_) s_rel[sub][tt] = nb_rels[r * M_ + tt];
        __syncthreads();
        if (tt < cnt && nb_nodes[r * M_ + tt] == 0) atomicAdd(&s_c0[sub], 1);

        float acc = 0.f;
        int m = 0;
        for (; m + 4 <= cnt; m += 4) {
            float v0 = rel_emb[s_rel[sub][m + 0] * E_ + tt];
            float v1 = rel_emb[s_rel[sub][m + 1] * E_ + tt];
            float v2 = rel_emb[s_rel[sub][m + 2] * E_ + tt];
            float v3 = rel_emb[s_rel[sub][m + 3] * E_ + tt];
            acc += (v0 + v1) + (v2 + v3);
        }
        for (; m < cnt; m++) acc += rel_emb[s_rel[sub][m] * E_ + tt];
        __syncthreads();

        float denom = (cnt == 0) ? 1.f : (float)cnt;
        g_relsum[r * E_ + tt] = acc / denom;
        if (tt == 0) {
            g_c0d[r] = (float)s_c0[sub] / denom;
            g_cd[r]  = (float)cnt / denom;
        }
    }
}

// ============================================================================
// Kernel 3 (warp-mma bf16, double-buffered BK=32): upd GEMM R=8192, N=128, K=256
//   BM=64, grid(128), block(256): 8 warps = 4 M-slices x 2 N-halves
// ============================================================================
__global__ __launch_bounds__(256)
void k3_upd(const int* __restrict__ aims, const float* __restrict__ ent,
            const float* __restrict__ hb, const float* __restrict__ pb)
{
    __shared__ __nv_bfloat16 As[2][64 * PITCH2];     // 2 x 5120 B
    __shared__ __nv_bfloat16 Bs[2][128 * PITCH2];    // 2 x 10240 B
    __shared__ const float* rowp[64];
    __shared__ float s_c0d[64], s_cd[64], s_hb[128], s_pb[128], s_pn[2 * 128];

    int t    = threadIdx.x;
    int wid  = t >> 5, lane = t & 31;
    int l4   = lane >> 2, lp2 = (lane & 3) * 2;
    int wrow = (wid & 3) * 16;
    int nb8  = (wid >> 2) * 8;
    int rr0  = blockIdx.x * 64;
    int b0   = rr0 >> 5;

    if (t < 64) {
        int rr = rr0 + t;
        rowp[t]  = ent + (long)aims[rr] * E_;
        s_c0d[t] = g_c0d[rr];
        s_cd[t]  = g_cd[rr];
    }
    if (t < 128) {
        s_hb[t] = hb[t];
        s_pb[t] = pb[t];
        s_pn[t] = g_pnode[b0 * H_ + t];
        s_pn[128 + t] = g_pnode[(b0 + 1) * H_ + t];
    }
    __syncthreads();

    // A tile: 64x32 -> 256 chunks / 256 t = 1;  B: 128x32 -> 512 chunks / 256 t = 2
    int aRow = t >> 2,        aC0 = (t & 3) * 8;
    int bRow0 = t >> 2,       bC0 = (t & 3) * 8;     // chunks 0..255
    int bRow1 = (t + 256) >> 2;                      // chunks 256..511 (same c0)

    uint32_t a_frag_off = (uint32_t)((wrow + (lane & 15)) * PITCH2 + ((lane >> 4) << 3)) * 2;
    uint32_t b_frag_off = (uint32_t)((nb8 * 8 + (lane & 7) + ((lane >> 4) << 3)) * PITCH2
                                     + (((lane >> 3) & 1) << 3)) * 2;

    float acc[32];
    #pragma unroll
    for (int i = 0; i < 32; i++) acc[i] = 0.f;

    uint4 aPf, bPf0, bPf1;
    // prefetch tile 0 (k 0..31, seg 0 = gathered aim rows)
    {
        const float* src = rowp[aRow] + aC0;
        aPf  = cvt8_bf16(*(const float4*)src, *(const float4*)(src + 4));
        bPf0 = *(const uint4*)(g_hpWb + bRow0 * 256 + bC0);
        bPf1 = *(const uint4*)(g_hpWb + bRow1 * 256 + bC0);
    }
    *(uint4*)(As[0] + aRow * PITCH2 + aC0)  = aPf;
    *(uint4*)(Bs[0] + bRow0 * PITCH2 + bC0) = bPf0;
    *(uint4*)(Bs[0] + bRow1 * PITCH2 + bC0) = bPf1;
    __syncthreads();

    #pragma unroll
    for (int j = 0; j < 8; j++) {
        int st = j & 1;
        if (j < 7) {
            int jn = j + 1;
            int kof = (jn & 3) * 32;
            const float* src = (jn < 4) ? (rowp[aRow] + kof + aC0)
                                        : (g_relsum + (rr0 + aRow) * E_ + kof + aC0);
            aPf  = cvt8_bf16(*(const float4*)src, *(const float4*)(src + 4));
            bPf0 = *(const uint4*)(g_hpWb + bRow0 * 256 + jn * 32 + bC0);
            bPf1 = *(const uint4*)(g_hpWb + bRow1 * 256 + jn * 32 + bC0);
        }
        uint32_t asb = smem_u32(As[st]), bsb = smem_u32(Bs[st]);
        #pragma unroll
        for (int ks = 0; ks < 2; ks++) {
            uint32_t kb = (uint32_t)(ks * 16) * 2;
            uint32_t a[4];
            ldm_x4(a, asb + a_frag_off + kb);
            #pragma unroll
            for (int p = 0; p < 4; p++) {
                uint32_t bq[4];
                ldm_x4(bq, bsb + b_frag_off + (uint32_t)(p * 16 * PITCH2) * 2 + kb);
                mma16816(acc + (p * 2) * 4,     a, bq);
                mma16816(acc + (p * 2 + 1) * 4, a, bq + 2);
            }
        }
        if (j < 7) {
            int sn = st ^ 1;
            *(uint4*)(As[sn] + aRow * PITCH2 + aC0)  = aPf;
            *(uint4*)(Bs[sn] + bRow0 * PITCH2 + bC0) = bPf0;
            *(uint4*)(Bs[sn] + bRow1 * PITCH2 + bC0) = bPf1;
            __syncthreads();
        }
    }

    // epilogue -> g_upd
    int r0 = wrow + l4, r1 = r0 + 8;
    int bi0 = (r0 >> 5) * 128, bi1 = (r1 >> 5) * 128;
    #pragma unroll
    for (int p2 = 0; p2 < 8; p2++) {
        int c0 = (nb8 + p2) * 8 + lp2, c1 = c0 + 1;
        g_upd[(rr0 + r0) * H_ + c0] =
            lrelu(acc[p2*4+0] + s_hb[c0] + s_c0d[r0] * s_pn[bi0 + c0] + s_cd[r0] * s_pb[c0]);
        g_upd[(rr0 + r0) * H_ + c1] =
            lrelu(acc[p2*4+1] + s_hb[c1] + s_c0d[r0] * s_pn[bi0 + c1] + s_cd[r0] * s_pb[c1]);
        g_upd[(rr0 + r1) * H_ + c0] =
            lrelu(acc[p2*4+2] + s_hb[c0] + s_c0d[r1] * s_pn[bi1 + c0] + s_cd[r1] * s_pb[c0]);
        g_upd[(rr0 + r1) * H_ + c1] =
            lrelu(acc[p2*4+3] + s_hb[c1] + s_c0d[r1] * s_pn[bi1 + c1] + s_cd[r1] * s_pb[c1]);
    }
}

// ============================================================================
// Kernel 4 (fused): cc = [cur;query]; gate -> out[:,MN]; state matvec
// ============================================================================
__global__ void k4_state(const int* __restrict__ currents, const float* __restrict__ query,
                         const float* __restrict__ gW, const float* __restrict__ gb,
                         const float* __restrict__ nbias, float* __restrict__ out)
{
    int b = blockIdx.x, t = threadIdx.x;
    __shared__ float cc[256];
    __shared__ float red[128];
    int c = currents[b];
    float cur;
    if (c == 0)                 cur = g_init[b * H_ + t];
    else if (c >= 1 && c <= K_) cur = g_upd[(b * K_ + (c - 1)) * H_ + t];
    else                        cur = 0.f;
    float q = query[b * Q_ + t];
    cc[t]       = cur;
    cc[128 + t] = q;
    red[t] = gW[t] * cur + gW[128 + t] * q;
    __syncthreads();
    for (int s = 64; s > 0; s >>= 1) {
        if (t < s) red[t] += red[t + s];
        __syncthreads();
    }
    if (t == 0) out[b * (MN_ + 1) + MN_] = red[0] + gb[0];

    float acc = 0.f;
    #pragma unroll 8
    for (int e = 0; e < 256; e++) acc += cc[e] * g_nWT[e * 128 + t];
    g_state[b * H_ + t] = lrelu(acc + nbias[t]);
}

// ============================================================================
// Kernel 5 (warp-mma bf16, double-buffered BK=32): candidate GEMM + epilogue
//   BM=128, grid(512), block(512): 16 warps = 8 M-slices x 2 N-halves
// ============================================================================
__global__ __launch_bounds__(512)
void k5_cand(const int* __restrict__ cnodes, const int* __restrict__ cents,
             const int* __restrict__ crels, const int* __restrict__ cmask,
             const float* __restrict__ ent, const float* __restrict__ rel,
             const float* __restrict__ cb, float* __restrict__ out)
{
    __shared__ __nv_bfloat16 As[2][128 * PITCH2];    // 2 x 10240 B
    __shared__ __nv_bfloat16 Bs[2][128 * PITCH2];    // 2 x 10240 B
    __shared__ const float* pN[128];
    __shared__ const float* pE[128];
    __shared__ const float* pR[128];
    __shared__ float s_state[H_], s_cb[H_];
    __shared__ float sred[16][16];

    int t    = threadIdx.x;
    int wid  = t >> 5, lane = t & 31;
    int l4   = lane >> 2, lp2 = (lane & 3) * 2;
    int wrow = (wid & 7) * 16;
    int nb8  = (wid >> 3) * 8;
    int rr0  = blockIdx.x * 128;
    int b    = rr0 >> 8;

    if (t < 128) {
        int rr = rr0 + t;
        int node = cnodes[rr];
        const float* p;
        if (node == 0)                    p = g_init + b * H_;
        else if (node >= 1 && node <= K_) p = g_upd + (b * K_ + (node - 1)) * H_;
        else                              p = g_zero;
        pN[t] = p;
        pE[t] = ent + (long)cents[rr] * E_;
        pR[t] = rel + (long)crels[rr] * E_;
        s_state[t] = g_state[b * H_ + t];
        s_cb[t]    = cb[t];
    }
    __syncthreads();

    // A/B tiles: 128x32 -> 512 chunks / 512 t = 1 each
    int aRow = t >> 2, aC0 = (t & 3) * 8;

    uint32_t a_frag_off = (uint32_t)((wrow + (lane & 15)) * PITCH2 + ((lane >> 4) << 3)) * 2;
    uint32_t b_frag_off = (uint32_t)((nb8 * 8 + (lane & 7) + ((lane >> 4) << 3)) * PITCH2
                                     + (((lane >> 3) & 1) << 3)) * 2;

    float acc[32];
    #pragma unroll
    for (int i = 0; i < 32; i++) acc[i] = 0.f;

    uint4 aPf, bPf;
    {
        const float* src = pN[aRow] + aC0;
        aPf = cvt8_bf16(*(const float4*)src, *(const float4*)(src + 4));
        bPf = *(const uint4*)(g_cWb + aRow * 384 + aC0);
    }
    *(uint4*)(As[0] + aRow * PITCH2 + aC0) = aPf;
    *(uint4*)(Bs[0] + aRow * PITCH2 + aC0) = bPf;
    __syncthreads();

    #pragma unroll
    for (int j = 0; j < 12; j++) {
        int st = j & 1;
        if (j < 11) {
            int jn = j + 1;
            int seg = jn >> 2, kof = (jn & 3) * 32;
            const float* const* ptab = (seg == 0) ? pN : (seg == 1) ? pE : pR;
            const float* src = ptab[aRow] + kof + aC0;
            aPf = cvt8_bf16(*(const float4*)src, *(const float4*)(src + 4));
            bPf = *(const uint4*)(g_cWb + aRow * 384 + jn * 32 + aC0);
        }
        uint32_t asb = smem_u32(As[st]), bsb = smem_u32(Bs[st]);
        #pragma unroll
        for (int ks = 0; ks < 2; ks++) {
            uint32_t kb = (uint32_t)(ks * 16) * 2;
            uint32_t a[4];
            ldm_x4(a, asb + a_frag_off + kb);
            #pragma unroll
            for (int p = 0; p < 4; p++) {
                uint32_t bq[4];
                ldm_x4(bq, bsb + b_frag_off + (uint32_t)(p * 16 * PITCH2) * 2 + kb);
                mma16816(acc + (p * 2) * 4,     a, bq);
                mma16816(acc + (p * 2 + 1) * 4, a, bq + 2);
            }
        }
        if (j < 11) {
            int sn = st ^ 1;
            *(uint4*)(As[sn] + aRow * PITCH2 + aC0) = aPf;
            *(uint4*)(Bs[sn] + aRow * PITCH2 + aC0) = bPf;
            __syncthreads();
        }
    }

    // epilogue: lrelu+bias, dot(state), quad-reduce, cross-warp reduce
    float rlo = 0.f, rhi = 0.f;
    #pragma unroll
    for (int p2 = 0; p2 < 8; p2++) {
        int c0 = (nb8 + p2) * 8 + lp2, c1 = c0 + 1;
        rlo += lrelu(acc[p2 * 4 + 0] + s_cb[c0]) * s_state[c0]
             + lrelu(acc[p2 * 4 + 1] + s_cb[c1]) * s_state[c1];
        rhi += lrelu(acc[p2 * 4 + 2] + s_cb[c0]) * s_state[c0]
             + lrelu(acc[p2 * 4 + 3] + s_cb[c1]) * s_state[c1];
    }
    rlo += __shfl_xor_sync(0xFFFFFFFFu, rlo, 1);
    rlo += __shfl_xor_sync(0xFFFFFFFFu, rlo, 2);
    rhi += __shfl_xor_sync(0xFFFFFFFFu, rhi, 1);
    rhi += __shfl_xor_sync(0xFFFFFFFFu, rhi, 2);
    __syncthreads();
    if ((lane & 3) == 0) {
        sred[wid][l4]     = rlo;
        sred[wid][l4 + 8] = rhi;
    }
    __syncthreads();

    if (t < 128) {
        int w = t >> 4, r = t & 15;
        float s = (sred[w][r] + sred[w + 8][r]) * 0.08838834764831845f;  // 1/sqrt(128)
        int rr = rr0 + w * 16 + r;
        out[b * (MN_ + 1) + (rr & 255)] = cmask[rr] ? s : -100000.f;
    }
}

// ============================================================================
// launch
// ============================================================================
extern "C" void kernel_launch(void* const* d_in, const int* in_sizes, int n_in,
                              void* d_out, int out_size)
{
    const int*   start_entities      = (const int*)  d_in[0];
    const int*   aims                = (const int*)  d_in[1];
    /* node_pos = d_in[2]: arange(1..K), folded into indexing */
    const int*   neighbor_nodes      = (const int*)  d_in[3];
    const int*   neighbor_relations  = (const int*)  d_in[4];
    const int*   neighbors_num       = (const int*)  d_in[5];
    const int*   currents            = (const int*)  d_in[6];
    const int*   candidate_nodes     = (const int*)  d_in[7];
    const int*   candidate_entities  = (const int*)  d_in[8];
    const int*   candidate_relations = (const int*)  d_in[9];
    const int*   candidate_masks     = (const int*)  d_in[10];   // bool -> int32
    const float* entity_emb          = (const float*)d_in[11];
    const float* relation_emb        = (const float*)d_in[12];
    const float* hidden_W            = (const float*)d_in[13];
    const float* hidden_b            = (const float*)d_in[14];
    const float* pass_W              = (const float*)d_in[15];
    const float* pass_b              = (const float*)d_in[16];
    const float* nexthop_W           = (const float*)d_in[17];
    const float* nexthop_b           = (const float*)d_in[18];
    const float* candidate_W         = (const float*)d_in[19];
    const float* candidate_b         = (const float*)d_in[20];
    const float* gate_W              = (const float*)d_in[21];
    const float* gate_b              = (const float*)d_in[22];
    const float* query               = (const float*)d_in[23];
    float* out = (float*)d_out;

    ksetup   <<<4800, 256>>>(candidate_W, hidden_W, pass_W, nexthop_W,
                             start_entities, entity_emb, hidden_b,
                             neighbor_nodes, neighbor_relations, neighbors_num, relation_emb);
    k3_upd   <<<128, 256>>>(aims, entity_emb, hidden_b, pass_b);
    k4_state <<<B_, 128>>>(currents, query, gate_W, gate_b, nexthop_b, out);
    k5_cand  <<<(B_ * MN_) / 128, 512>>>(candidate_nodes, candidate_entities,
                                         candidate_relations, candidate_masks,
                                         entity_emb, relation_emb, candidate_b, out);
}

// round 9
// speedup vs baseline: 3.3272x; 1.1417x over previous
#include <cuda_runtime.h>
#include <cuda_bf16.h>
#include <cstdint>

// ---------------- problem constants ----------------
#define B_   256
#define K_   32
#define M_   64
#define MN_  256
#define E_   128
#define H_   128
#define Q_   128

// ---------------- scratch (device globals) ----------------
__device__ float g_init  [B_ * H_];
__device__ float g_pnode [B_ * H_];
__device__ float g_relsum[B_ * K_ * E_];
__device__ float g_c0d   [B_ * K_];
__device__ float g_cd    [B_ * K_];
__device__ float g_upd   [B_ * K_ * H_];
__device__ float g_state [B_ * H_];
__device__ float g_nWT   [(H_ + Q_) * H_];        // nexthop_W transposed
__device__ float g_zero  [H_];                    // stays zero
__device__ __nv_bfloat16 g_cWb [H_ * 384];        // candidate_W in bf16
__device__ __nv_bfloat16 g_hpWb[H_ * 256];        // [hidden_W | pass_W[:,128:]] bf16

__device__ __forceinline__ float lrelu(float x) { return x >= 0.f ? x : 0.01f * x; }

__device__ __forceinline__ uint32_t smem_u32(const void* p) {
    uint32_t a;
    asm("{ .reg .u64 t; cvta.to.shared.u64 t, %1; cvt.u32.u64 %0, t; }" : "=r"(a) : "l"(p));
    return a;
}
__device__ __forceinline__ void mma16816(float* c, const uint32_t* a, const uint32_t* b) {
    asm volatile(
        "mma.sync.aligned.m16n8k16.row.col.f32.bf16.bf16.f32 "
        "{%0,%1,%2,%3}, {%4,%5,%6,%7}, {%8,%9}, {%0,%1,%2,%3};"
        : "+f"(c[0]), "+f"(c[1]), "+f"(c[2]), "+f"(c[3])
        : "r"(a[0]), "r"(a[1]), "r"(a[2]), "r"(a[3]), "r"(b[0]), "r"(b[1]));
}
__device__ __forceinline__ void ldm_x4(uint32_t* r, uint32_t addr) {
    asm volatile("ldmatrix.sync.aligned.m8n8.x4.shared.b16 {%0,%1,%2,%3}, [%4];"
        : "=r"(r[0]), "=r"(r[1]), "=r"(r[2]), "=r"(r[3]) : "r"(addr));
}
__device__ __forceinline__ uint4 cvt8_bf16(float4 va, float4 vb) {
    __nv_bfloat162 p0 = __floats2bfloat162_rn(va.x, va.y);
    __nv_bfloat162 p1 = __floats2bfloat162_rn(va.z, va.w);
    __nv_bfloat162 p2 = __floats2bfloat162_rn(vb.x, vb.y);
    __nv_bfloat162 p3 = __floats2bfloat162_rn(vb.z, vb.w);
    uint4 u;
    u.x = *(uint32_t*)&p0; u.y = *(uint32_t*)&p1;
    u.z = *(uint32_t*)&p2; u.w = *(uint32_t*)&p3;
    return u;
}
#define CP16(dst, src) \
    asm volatile("cp.async.cg.shared.global [%0], [%1], 16;" :: "r"(dst), "l"(src) : "memory")
#define CPC()  asm volatile("cp.async.commit_group;" ::: "memory")
#define CPW0() asm volatile("cp.async.wait_group 0;" ::: "memory")

#define PITCH2 40   // 32 bf16 + 8 pad: rows at 80B -> distinct banks for ldmatrix

// ============================================================================
// Setup kernel: blocks [0,448) weight prep | [448,704) init/pnode | [704,4800) relsum
// ============================================================================
__global__ __launch_bounds__(256)
void ksetup(const float* __restrict__ cW, const float* __restrict__ hW,
            const float* __restrict__ pW, const float* __restrict__ nW,
            const int* __restrict__ start, const float* __restrict__ ent,
            const float* __restrict__ hb,
            const int* __restrict__ nb_nodes, const int* __restrict__ nb_rels,
            const int* __restrict__ nb_num, const float* __restrict__ rel_emb)
{
    int blk = blockIdx.x, t = threadIdx.x;

    if (blk < 448) {
        int i = blk * 256 + t;
        if (i < 49152) {
            g_cWb[i] = __float2bfloat16(cW[i]);
        } else if (i < 81920) {
            int j = i - 49152;
            int n = j >> 8, k = j & 255;
            g_hpWb[j] = __float2bfloat16(k < 128 ? hW[n * 128 + k] : pW[n * 256 + k]);
        } else {
            int m = i - 81920;
            int e = m >> 7, n = m & 127;
            g_nWT[m] = nW[n * 256 + e];
        }
        return;
    }

    if (blk < 704) {
        int b = blk - 448;
        __shared__ float xs[E_], iv[H_];
        if (t < 128) xs[t] = ent[(long)start[b] * E_ + t];
        __syncthreads();
        if (t < 128) {
            float acc = 0.f;
            const float* wr = hW + t * E_;
            #pragma unroll 8
            for (int e = 0; e < E_; e++) acc += wr[e] * xs[e];
            float v = lrelu(acc + hb[t]);
            iv[t] = v;
            g_init[b * H_ + t] = v;
        }
        __syncthreads();
        if (t < 128) {
            float p = 0.f;
            const float* pr = pW + t * (H_ + E_);
            #pragma unroll 8
            for (int e = 0; e < H_; e++) p += pr[e] * iv[e];
            g_pnode[b * H_ + t] = p;
        }
        return;
    }

    {
        __shared__ int s_rel[2][M_];
        __shared__ int s_c0[2];
        int sub = t >> 7, tt = t & 127;
        int r = (blk - 704) * 2 + sub;
        if (tt == 0) s_c0[sub] = 0;
        int cnt = nb_num[r];
        if (cnt < 0)  cnt = 0;
        if (cnt > M_) cnt = M_;
        if (tt < M_) s_rel[sub][tt] = nb_rels[r * M_ + tt];
        __syncthreads();
        if (tt < cnt && nb_nodes[r * M_ + tt] == 0) atomicAdd(&s_c0[sub], 1);

        float acc = 0.f;
        int m = 0;
        for (; m + 4 <= cnt; m += 4) {
            float v0 = rel_emb[s_rel[sub][m + 0] * E_ + tt];
            float v1 = rel_emb[s_rel[sub][m + 1] * E_ + tt];
            float v2 = rel_emb[s_rel[sub][m + 2] * E_ + tt];
            float v3 = rel_emb[s_rel[sub][m + 3] * E_ + tt];
            acc += (v0 + v1) + (v2 + v3);
        }
        for (; m < cnt; m++) acc += rel_emb[s_rel[sub][m] * E_ + tt];
        __syncthreads();

        float denom = (cnt == 0) ? 1.f : (float)cnt;
        g_relsum[r * E_ + tt] = acc / denom;
        if (tt == 0) {
            g_c0d[r] = (float)s_c0[sub] / denom;
            g_cd[r]  = (float)cnt / denom;
        }
    }
}

// ============================================================================
// Kernel 3 (warp-mma bf16, 32x32 warp tiles, cp.async B): upd GEMM
//   R=8192, N=128, K=256.  BM=64, grid(128), block(256):
//   8 warps = 2 M-slices x 4 N-quarters, double-buffered BK=32
// ============================================================================
__global__ __launch_bounds__(256)
void k3_upd(const int* __restrict__ aims, const float* __restrict__ ent,
            const float* __restrict__ hb, const float* __restrict__ pb)
{
    __shared__ __nv_bfloat16 As[2][64 * PITCH2];     // 2 x 5120 B
    __shared__ __nv_bfloat16 Bs[2][128 * PITCH2];    // 2 x 10240 B
    __shared__ const float* rowp[64];
    __shared__ float s_c0d[64], s_cd[64], s_hb[128], s_pb[128], s_pn[2 * 128];

    int t    = threadIdx.x;
    int wid  = t >> 5, lane = t & 31;
    int l4   = lane >> 2, lp2 = (lane & 3) * 2;
    int wm   = wid & 1, wn = wid >> 1;
    int rr0  = blockIdx.x * 64;
    int b0   = rr0 >> 5;

    if (t < 64) {
        int rr = rr0 + t;
        rowp[t]  = ent + (long)aims[rr] * E_;
        s_c0d[t] = g_c0d[rr];
        s_cd[t]  = g_cd[rr];
    }
    if (t < 128) {
        s_hb[t] = hb[t];
        s_pb[t] = pb[t];
        s_pn[t] = g_pnode[b0 * H_ + t];
        s_pn[128 + t] = g_pnode[(b0 + 1) * H_ + t];
    }
    __syncthreads();

    int aRow  = t >> 2, aC0 = (t & 3) * 8;           // A: 64x32, 1 chunk/thread
    int bRow0 = t >> 2, bRow1 = 64 + (t >> 2);       // B: 128x32, 2 chunks/thread
    uint32_t bSm0 = (uint32_t)(bRow0 * PITCH2 + aC0) * 2;
    uint32_t bSm1 = (uint32_t)(bRow1 * PITCH2 + aC0) * 2;

    uint32_t a_off = (uint32_t)((wm * 32 + (lane & 15)) * PITCH2 + ((lane >> 4) << 3)) * 2;
    uint32_t b_off = (uint32_t)((wn * 32 + (lane & 7) + ((lane >> 4) << 3)) * PITCH2
                                + (((lane >> 3) & 1) << 3)) * 2;
    const uint32_t STEP16 = (uint32_t)(16 * PITCH2) * 2;

    float acc[32];
    #pragma unroll
    for (int i = 0; i < 32; i++) acc[i] = 0.f;

    // tile 0: A via regs, B via cp.async
    {
        const float* src = rowp[aRow] + aC0;
        uint4 a0 = cvt8_bf16(*(const float4*)src, *(const float4*)(src + 4));
        uint32_t bdst = smem_u32(Bs[0]);
        CP16(bdst + bSm0, g_hpWb + bRow0 * 256 + aC0);
        CP16(bdst + bSm1, g_hpWb + bRow1 * 256 + aC0);
        CPC();
        *(uint4*)(As[0] + aRow * PITCH2 + aC0) = a0;
        CPW0();
    }
    __syncthreads();

    uint4 aPf;
    #pragma unroll
    for (int j = 0; j < 8; j++) {
        int st = j & 1;
        if (j < 7) {
            int jn = j + 1;
            int kof = (jn & 3) * 32;
            const float* src = (jn < 4) ? (rowp[aRow] + kof + aC0)
                                        : (g_relsum + (rr0 + aRow) * E_ + kof + aC0);
            aPf = cvt8_bf16(*(const float4*)src, *(const float4*)(src + 4));
            uint32_t bdst = smem_u32(Bs[st ^ 1]);
            CP16(bdst + bSm0, g_hpWb + bRow0 * 256 + jn * 32 + aC0);
            CP16(bdst + bSm1, g_hpWb + bRow1 * 256 + jn * 32 + aC0);
            CPC();
        }
        uint32_t asb = smem_u32(As[st]), bsb = smem_u32(Bs[st]);
        #pragma unroll
        for (int ks = 0; ks < 2; ks++) {
            uint32_t kb = (uint32_t)(ks * 16) * 2;
            uint32_t a0[4], a1[4], b0[4], b1[4];
            ldm_x4(a0, asb + a_off + kb);
            ldm_x4(a1, asb + a_off + STEP16 + kb);
            ldm_x4(b0, bsb + b_off + kb);
            ldm_x4(b1, bsb + b_off + STEP16 + kb);
            mma16816(acc + 0,  a0, b0);  mma16816(acc + 4,  a0, b0 + 2);
            mma16816(acc + 8,  a0, b1);  mma16816(acc + 12, a0, b1 + 2);
            mma16816(acc + 16, a1, b0);  mma16816(acc + 20, a1, b0 + 2);
            mma16816(acc + 24, a1, b1);  mma16816(acc + 28, a1, b1 + 2);
        }
        if (j < 7) {
            *(uint4*)(As[st ^ 1] + aRow * PITCH2 + aC0) = aPf;
            CPW0();
            __syncthreads();
        }
    }

    // epilogue -> g_upd
    #pragma unroll
    for (int mi = 0; mi < 2; mi++) {
        int rl0 = wm * 32 + mi * 16 + l4, rl1 = rl0 + 8;
        int bi0 = (rl0 >> 5) * 128, bi1 = (rl1 >> 5) * 128;
        #pragma unroll
        for (int ni = 0; ni < 4; ni++) {
            int c0 = wn * 32 + ni * 8 + lp2, c1 = c0 + 1;
            const float* a = acc + mi * 16 + ni * 4;
            g_upd[(rr0 + rl0) * H_ + c0] =
                lrelu(a[0] + s_hb[c0] + s_c0d[rl0] * s_pn[bi0 + c0] + s_cd[rl0] * s_pb[c0]);
            g_upd[(rr0 + rl0) * H_ + c1] =
                lrelu(a[1] + s_hb[c1] + s_c0d[rl0] * s_pn[bi0 + c1] + s_cd[rl0] * s_pb[c1]);
            g_upd[(rr0 + rl1) * H_ + c0] =
                lrelu(a[2] + s_hb[c0] + s_c0d[rl1] * s_pn[bi1 + c0] + s_cd[rl1] * s_pb[c0]);
            g_upd[(rr0 + rl1) * H_ + c1] =
                lrelu(a[3] + s_hb[c1] + s_c0d[rl1] * s_pn[bi1 + c1] + s_cd[rl1] * s_pb[c1]);
        }
    }
}

// ============================================================================
// Kernel 4 (fused): cc = [cur;query]; gate -> out[:,MN]; state matvec
// ============================================================================
__global__ void k4_state(const int* __restrict__ currents, const float* __restrict__ query,
                         const float* __restrict__ gW, const float* __restrict__ gb,
                         const float* __restrict__ nbias, float* __restrict__ out)
{
    int b = blockIdx.x, t = threadIdx.x;
    __shared__ float cc[256];
    __shared__ float red[128];
    int c = currents[b];
    float cur;
    if (c == 0)                 cur = g_init[b * H_ + t];
    else if (c >= 1 && c <= K_) cur = g_upd[(b * K_ + (c - 1)) * H_ + t];
    else                        cur = 0.f;
    float q = query[b * Q_ + t];
    cc[t]       = cur;
    cc[128 + t] = q;
    red[t] = gW[t] * cur + gW[128 + t] * q;
    __syncthreads();
    for (int s = 64; s > 0; s >>= 1) {
        if (t < s) red[t] += red[t + s];
        __syncthreads();
    }
    if (t == 0) out[b * (MN_ + 1) + MN_] = red[0] + gb[0];

    float acc = 0.f;
    #pragma unroll 8
    for (int e = 0; e < 256; e++) acc += cc[e] * g_nWT[e * 128 + t];
    g_state[b * H_ + t] = lrelu(acc + nbias[t]);
}

// ============================================================================
// Kernel 5 (warp-mma bf16, 32x32 warp tiles, cp.async B): candidate GEMM
//   R=65536, N=128, K=384.  BM=64, grid(1024), block(256):
//   8 warps = 2 M-slices x 4 N-quarters, double-buffered BK=32
// ============================================================================
__global__ __launch_bounds__(256)
void k5_cand(const int* __restrict__ cnodes, const int* __restrict__ cents,
             const int* __restrict__ crels, const int* __restrict__ cmask,
             const float* __restrict__ ent, const float* __restrict__ rel,
             const float* __restrict__ cb, float* __restrict__ out)
{
    __shared__ __nv_bfloat16 As[2][64 * PITCH2];     // 2 x 5120 B
    __shared__ __nv_bfloat16 Bs[2][128 * PITCH2];    // 2 x 10240 B
    __shared__ const float* pN[64];
    __shared__ const float* pE[64];
    __shared__ const float* pR[64];
    __shared__ float s_state[H_], s_cb[H_];
    __shared__ float sred[4][64];

    int t    = threadIdx.x;
    int wid  = t >> 5, lane = t & 31;
    int l4   = lane >> 2, lp2 = (lane & 3) * 2;
    int wm   = wid & 1, wn = wid >> 1;
    int rr0  = blockIdx.x * 64;
    int b    = rr0 >> 8;

    if (t < 64) {
        int rr = rr0 + t;
        int node = cnodes[rr];
        const float* p;
        if (node == 0)                    p = g_init + b * H_;
        else if (node >= 1 && node <= K_) p = g_upd + (b * K_ + (node - 1)) * H_;
        else                              p = g_zero;
        pN[t] = p;
        pE[t] = ent + (long)cents[rr] * E_;
        pR[t] = rel + (long)crels[rr] * E_;
    }
    if (t < 128) {
        s_state[t] = g_state[b * H_ + t];
        s_cb[t]    = cb[t];
    }
    __syncthreads();

    int aRow  = t >> 2, aC0 = (t & 3) * 8;           // A: 64x32, 1 chunk/thread
    int bRow0 = t >> 2, bRow1 = 64 + (t >> 2);       // B: 128x32, 2 chunks/thread
    uint32_t bSm0 = (uint32_t)(bRow0 * PITCH2 + aC0) * 2;
    uint32_t bSm1 = (uint32_t)(bRow1 * PITCH2 + aC0) * 2;

    uint32_t a_off = (uint32_t)((wm * 32 + (lane & 15)) * PITCH2 + ((lane >> 4) << 3)) * 2;
    uint32_t b_off = (uint32_t)((wn * 32 + (lane & 7) + ((lane >> 4) << 3)) * PITCH2
                                + (((lane >> 3) & 1) << 3)) * 2;
    const uint32_t STEP16 = (uint32_t)(16 * PITCH2) * 2;

    float acc[32];
    #pragma unroll
    for (int i = 0; i < 32; i++) acc[i] = 0.f;

    // tile 0
    {
        const float* src = pN[aRow] + aC0;
        uint4 a0 = cvt8_bf16(*(const float4*)src, *(const float4*)(src + 4));
        uint32_t bdst = smem_u32(Bs[0]);
        CP16(bdst + bSm0, g_cWb + bRow0 * 384 + aC0);
        CP16(bdst + bSm1, g_cWb + bRow1 * 384 + aC0);
        CPC();
        *(uint4*)(As[0] + aRow * PITCH2 + aC0) = a0;
        CPW0();
    }
    __syncthreads();

    uint4 aPf;
    #pragma unroll
    for (int j = 0; j < 12; j++) {
        int st = j & 1;
        if (j < 11) {
            int jn = j + 1;
            int seg = jn >> 2, kof = (jn & 3) * 32;
            const float* const* ptab = (seg == 0) ? pN : (seg == 1) ? pE : pR;
            const float* src = ptab[aRow] + kof + aC0;
            aPf = cvt8_bf16(*(const float4*)src, *(const float4*)(src + 4));
            uint32_t bdst = smem_u32(Bs[st ^ 1]);
            CP16(bdst + bSm0, g_cWb + bRow0 * 384 + jn * 32 + aC0);
            CP16(bdst + bSm1, g_cWb + bRow1 * 384 + jn * 32 + aC0);
            CPC();
        }
        uint32_t asb = smem_u32(As[st]), bsb = smem_u32(Bs[st]);
        #pragma unroll
        for (int ks = 0; ks < 2; ks++) {
            uint32_t kb = (uint32_t)(ks * 16) * 2;
            uint32_t a0[4], a1[4], b0[4], b1[4];
            ldm_x4(a0, asb + a_off + kb);
            ldm_x4(a1, asb + a_off + STEP16 + kb);
            ldm_x4(b0, bsb + b_off + kb);
            ldm_x4(b1, bsb + b_off + STEP16 + kb);
            mma16816(acc + 0,  a0, b0);  mma16816(acc + 4,  a0, b0 + 2);
            mma16816(acc + 8,  a0, b1);  mma16816(acc + 12, a0, b1 + 2);
            mma16816(acc + 16, a1, b0);  mma16816(acc + 20, a1, b0 + 2);
            mma16816(acc + 24, a1, b1);  mma16816(acc + 28, a1, b1 + 2);
        }
        if (j < 11) {
            *(uint4*)(As[st ^ 1] + aRow * PITCH2 + aC0) = aPf;
            CPW0();
            __syncthreads();
        }
    }

    // epilogue: lrelu+bias, dot(state), quad-reduce, cross-n-quarter reduce
    #pragma unroll
    for (int mi = 0; mi < 2; mi++) {
        float rl = 0.f, rh = 0.f;
        #pragma unroll
        for (int ni = 0; ni < 4; ni++) {
            int c0 = wn * 32 + ni * 8 + lp2, c1 = c0 + 1;
            const float* a = acc + mi * 16 + ni * 4;
            rl += lrelu(a[0] + s_cb[c0]) * s_state[c0] + lrelu(a[1] + s_cb[c1]) * s_state[c1];
            rh += lrelu(a[2] + s_cb[c0]) * s_state[c0] + lrelu(a[3] + s_cb[c1]) * s_state[c1];
        }
        rl += __shfl_xor_sync(0xFFFFFFFFu, rl, 1);
        rl += __shfl_xor_sync(0xFFFFFFFFu, rl, 2);
        rh += __shfl_xor_sync(0xFFFFFFFFu, rh, 1);
        rh += __shfl_xor_sync(0xFFFFFFFFu, rh, 2);
        if ((lane & 3) == 0) {
            sred[wn][wm * 32 + mi * 16 + l4]     = rl;
            sred[wn][wm * 32 + mi * 16 + l4 + 8] = rh;
        }
    }
    __syncthreads();

    if (t < 64) {
        float s = (sred[0][t] + sred[1][t] + sred[2][t] + sred[3][t])
                  * 0.08838834764831845f;          // 1/sqrt(128)
        int rr = rr0 + t;
        out[b * (MN_ + 1) + (rr & 255)] = cmask[rr] ? s : -100000.f;
    }
}

// ============================================================================
// launch
// ============================================================================
extern "C" void kernel_launch(void* const* d_in, const int* in_sizes, int n_in,
                              void* d_out, int out_size)
{
    const int*   start_entities      = (const int*)  d_in[0];
    const int*   aims                = (const int*)  d_in[1];
    /* node_pos = d_in[2]: arange(1..K), folded into indexing */
    const int*   neighbor_nodes      = (const int*)  d_in[3];
    const int*   neighbor_relations  = (const int*)  d_in[4];
    const int*   neighbors_num       = (const int*)  d_in[5];
    const int*   currents            = (const int*)  d_in[6];
    const int*   candidate_nodes     = (const int*)  d_in[7];
    const int*   candidate_entities  = (const int*)  d_in[8];
    const int*   candidate_relations = (const int*)  d_in[9];
    const int*   candidate_masks     = (const int*)  d_in[10];   // bool -> int32
    const float* entity_emb          = (const float*)d_in[11];
    const float* relation_emb        = (const float*)d_in[12];
    const float* hidden_W            = (const float*)d_in[13];
    const float* hidden_b            = (const float*)d_in[14];
    const float* pass_W              = (const float*)d_in[15];
    const float* pass_b              = (const float*)d_in[16];
    const float* nexthop_W           = (const float*)d_in[17];
    const float* nexthop_b           = (const float*)d_in[18];
    const float* candidate_W         = (const float*)d_in[19];
    const float* candidate_b         = (const float*)d_in[20];
    const float* gate_W              = (const float*)d_in[21];
    const float* gate_b              = (const float*)d_in[22];
    const float* query               = (const float*)d_in[23];
    float* out = (float*)d_out;

    ksetup   <<<4800, 256>>>(candidate_W, hidden_W, pass_W, nexthop_W,
                             start_entities, entity_emb, hidden_b,
                             neighbor_nodes, neighbor_relations, neighbors_num, relation_emb);
    k3_upd   <<<128, 256>>>(aims, entity_emb, hidden_b, pass_b);
    k4_state <<<B_, 128>>>(currents, query, gate_W, gate_b, nexthop_b, out);
    k5_cand  <<<(B_ * MN_) / 64, 256>>>(candidate_nodes, candidate_entities,
                                        candidate_relations, candidate_masks,
                                        entity_emb, relation_emb, candidate_b, out);
}